// round 11
// baseline (speedup 1.0000x reference)
#include <cuda_runtime.h>
#include <cuda_bf16.h>
#include <cuda_fp16.h>
#include <cstdint>

#define NV   40968           // total vertices (B*V)
#define VPER 10242
#define XSTR 392             // padded row stride of X0 (387 used)
#define PTOT 2132480         // total floats in P tables

// P table offsets (floats) per feature map: B*HW*128 cumulative
#define POFF0 0
#define POFF1 1605632
#define POFF2 2007040
#define POFF3 2107392

// weight images: 41 images (layer0: 13 chunks, layers1-7: 4 each), each
// 8192 uint32 words (hi 4096 | lo 4096) in mma fragment layout.
#define NIMG 41

// ---------------- device scratch (module globals; no allocations) --------
__device__ float g_P[PTOT];
__device__ float g_X0[(size_t)NV * XSTR];
__device__ float g_bufA[(size_t)NV * 128];
__device__ float g_bufB[(size_t)NV * 128];
__device__ float g_H1[(size_t)NV * 128];
__device__ float g_H2[(size_t)NV * 128];
__device__ int   g_cnt[NV];
__device__ int   g_offs[NV + 1];
__device__ int   g_entries[245760];
__device__ __align__(16) uint32_t g_pack[NIMG * 8192];

// ---------------- f32x2 helpers (precompute kernel) ----------------
__device__ __forceinline__ unsigned long long dup2(float x) {
    unsigned long long r;
    asm("mov.b64 %0, {%1, %1};" : "=l"(r) : "f"(x));
    return r;
}
__device__ __forceinline__ void ffma2(unsigned long long &d, unsigned long long a, unsigned long long b) {
    asm("fma.rn.f32x2 %0, %1, %2, %0;" : "+l"(d) : "l"(a), "l"(b));
}
__device__ __forceinline__ float2 unpk(unsigned long long v) {
    float2 r;
    asm("mov.b64 {%0, %1}, %2;" : "=f"(r.x), "=f"(r.y) : "l"(v));
    return r;
}

// fp16 mma m16n8k16, f32 accumulate
__device__ __forceinline__ void mma_f16(float* d, const uint32_t* a, const uint32_t* b) {
    asm("mma.sync.aligned.m16n8k16.row.col.f32.f16.f16.f32 "
        "{%0,%1,%2,%3},{%4,%5,%6,%7},{%8,%9},{%0,%1,%2,%3};"
        : "+f"(d[0]), "+f"(d[1]), "+f"(d[2]), "+f"(d[3])
        : "r"(a[0]), "r"(a[1]), "r"(a[2]), "r"(a[3]), "r"(b[0]), "r"(b[1]));
}
__device__ __forceinline__ uint32_t pack_h2(__half a, __half b) {
    __half2 h2 = __halves2half2(a, b);
    return *(uint32_t*)&h2;
}

// =========================================================================
// zero kernels
// =========================================================================
__global__ void zero_cnt_kernel()
{
    int i = blockIdx.x * blockDim.x + threadIdx.x;
    if (i < NV) g_cnt[i] = 0;
}
__global__ void zero_P_kernel()
{
    int i = blockIdx.x * blockDim.x + threadIdx.x;
    if (i < PTOT / 4) ((float4*)g_P)[i] = make_float4(0.f, 0.f, 0.f, 0.f);
}

// =========================================================================
// Weight prepack -> fragment-layout hi/lo fp16 images.
// =========================================================================
__global__ void prepack_weights(
    const float* __restrict__ g0w0, const float* __restrict__ g0w1,
    const float* __restrict__ gw0,  const float* __restrict__ gw1)
{
    int idx = blockIdx.x * 256 + threadIdx.x;
    if (idx >= NIMG * 4096) return;
    int img = idx >> 12;
    int e   = idx & 4095;
    int n   = e >> 4;          // 0..255
    int kp  = e & 15;          // k-pair 0..15 (k = 2*kp)

    const float *W0, *W1; int Kin, chunk;
    if (img < 13) { W0 = g0w0; W1 = g0w1; Kin = 387; chunk = img; }
    else {
        int t = img - 13;
        int L = t >> 2; chunk = t & 3;
        W0 = gw0 + (size_t)L * 16384;
        W1 = gw1 + (size_t)L * 16384;
        Kin = 128;
    }
    const float* W = (n < 128) ? W0 : W1;
    int col = n & 127;
    int kg = chunk * 32 + kp * 2;
    float w0v = (kg     < Kin) ? W[(size_t)kg * 128 + col]       : 0.f;
    float w1v = (kg + 1 < Kin) ? W[(size_t)(kg + 1) * 128 + col] : 0.f;

    __half h0 = __float2half_rn(w0v);
    __half l0 = __float2half_rn(w0v - __half2float(h0));
    __half h1 = __float2half_rn(w1v);
    __half l1 = __float2half_rn(w1v - __half2float(h1));

    int Ni = n >> 3, nn = n & 7;
    int kk = kp * 2;
    int Ks = kk >> 4;
    int kk16 = kk & 15;
    int rg = (kk16 >= 8) ? 1 : 0;
    int t  = (kk16 & 7) >> 1;
    int word = ((Ni * 2 + Ks) * 32 + nn * 4 + t) * 2 + rg;
    size_t base = (size_t)img * 8192;
    g_pack[base + word]        = pack_h2(h0, h1);
    g_pack[base + 4096 + word] = pack_h2(l0, l1);
}

// =========================================================================
// Kernel 1: per-pixel projection, split-K balanced, atomicAdd epilogue.
// =========================================================================
__global__ void __launch_bounds__(128) precompute_kernel(
    const float* __restrict__ f1, const float* __restrict__ f2,
    const float* __restrict__ f3, const float* __restrict__ f4,
    const float* __restrict__ BW)
{
    __shared__ float As[32][68];
    __shared__ float Bs[32][128];

    int bid = blockIdx.x;
    int m, local;
    if (bid < 196)      { m = 0; local = bid; }
    else if (bid < 300) { m = 1; local = bid - 196; }
    else if (bid < 364) { m = 2; local = bid - 300; }
    else                { m = 3; local = bid - 364; }

    const float* fm;
    int HW, C, WO, ks; size_t poff;
    if (m == 0)      { fm = f1; HW = 3136; C = 256;  WO = 0;    poff = POFF0; ks = 1; }
    else if (m == 1) { fm = f2; HW = 784;  C = 512;  WO = 256;  poff = POFF1; ks = 2; }
    else if (m == 2) { fm = f3; HW = 196;  C = 1024; WO = 768;  poff = POFF2; ks = 4; }
    else             { fm = f4; HW = 49;   C = 2048; WO = 1792; poff = POFF3; ks = 8; }

    int kt   = local % ks;
    int rest = local / ks;
    int b  = rest & 3;
    int mt = rest >> 2;

    int p0  = mt * 64;
    int kc0 = kt * 256;
    int tid = threadIdx.x;
    int rowg = tid & 7;
    int colg = tid >> 3;
    int r0 = rowg * 8;
    int c0 = colg * 8;

    unsigned long long acc[8][4];
#pragma unroll
    for (int i = 0; i < 8; i++)
#pragma unroll
        for (int j = 0; j < 4; j++) acc[i][j] = 0ULL;

    for (int ch = 0; ch < 8; ch++) {
        int kk = kc0 + ch * 32;
#pragma unroll
        for (int i = 0; i < 16; i++) {
            int lin = tid + i * 128;
            int c = lin >> 6;
            int p = lin & 63;
            float v = 0.f;
            if (p0 + p < HW)
                v = fm[((size_t)b * C + (kk + c)) * HW + p0 + p];
            As[c][p] = v;
        }
#pragma unroll
        for (int i = 0; i < 8; i++) {
            int lin4 = tid + i * 128;
            int k = lin4 >> 5;
            int n4 = (lin4 & 31) * 4;
            float4 v = *(const float4*)&BW[(size_t)(WO + kk + k) * 128 + n4];
            *(float4*)&Bs[k][n4] = v;
        }
        __syncthreads();
#pragma unroll 2
        for (int k = 0; k < 32; k++) {
            float4 aA = *(const float4*)&As[k][r0];
            float4 aB = *(const float4*)&As[k][r0 + 4];
            unsigned long long ad[8] = {dup2(aA.x), dup2(aA.y), dup2(aA.z), dup2(aA.w),
                                        dup2(aB.x), dup2(aB.y), dup2(aB.z), dup2(aB.w)};
            ulonglong2 bp0 = *(const ulonglong2*)&Bs[k][c0];
            ulonglong2 bp1 = *(const ulonglong2*)&Bs[k][c0 + 4];
            unsigned long long bb[4] = {bp0.x, bp0.y, bp1.x, bp1.y};
#pragma unroll
            for (int i = 0; i < 8; i++)
#pragma unroll
                for (int j = 0; j < 4; j++) ffma2(acc[i][j], ad[i], bb[j]);
        }
        __syncthreads();
    }
    size_t pbase = poff + (size_t)b * HW * 128;
#pragma unroll
    for (int i = 0; i < 8; i++) {
        int pix = p0 + r0 + i;
        if (pix >= HW) continue;
        float* dst = &g_P[pbase + (size_t)pix * 128 + c0];
        if (ks == 1) {
#pragma unroll
            for (int j = 0; j < 2; j++) {
                float2 vA = unpk(acc[i][j * 2]);
                float2 vB = unpk(acc[i][j * 2 + 1]);
                *(float4*)&dst[j * 4] = make_float4(vA.x, vA.y, vB.x, vB.y);
            }
        } else {
#pragma unroll
            for (int j = 0; j < 4; j++) {
                float2 v = unpk(acc[i][j]);
                atomicAdd(&dst[j * 2 + 0], v.x);
                atomicAdd(&dst[j * 2 + 1], v.y);
            }
        }
    }
}

// =========================================================================
// Kernel 2: bilinear sampler + bias + relu + assemble X0 row
// =========================================================================
__global__ void sampler_kernel(
    const float* __restrict__ av, const float* __restrict__ vp,
    const float* __restrict__ enc, const float* __restrict__ bias)
{
    int gwarp = (blockIdx.x * blockDim.x + threadIdx.x) >> 5;
    int lane = threadIdx.x & 31;
    if (gwarp >= NV) return;
    int v = gwarp;
    int b = v / VPER;

    float gx = av[(size_t)v * 3 + 0];
    float gy = av[(size_t)v * 3 + 1];

    float4 acc = make_float4(0.f, 0.f, 0.f, 0.f);
#pragma unroll
    for (int m = 0; m < 4; m++) {
        const int DIMm = (m == 0) ? 56 : (m == 1) ? 28 : (m == 2) ? 14 : 7;
        const int HWm  = DIMm * DIMm;
        const size_t POm = (m == 0) ? POFF0 : (m == 1) ? POFF1 : (m == 2) ? POFF2 : POFF3;
        int w = DIMm;
        float fx = (gx + 1.f) * 0.5f * (float)(w - 1);
        float fy = (gy + 1.f) * 0.5f * (float)(w - 1);
        float x0f = floorf(fx), y0f = floorf(fy);
        float wx1 = fx - x0f, wy1 = fy - y0f;
        float wx0 = 1.f - wx1, wy0 = 1.f - wy1;
        int x0 = min(max((int)x0f, 0), w - 1);
        int x1 = min(max((int)x0f + 1, 0), w - 1);
        int y0 = min(max((int)y0f, 0), w - 1);
        int y1 = min(max((int)y0f + 1, 0), w - 1);
        size_t base = POm + (size_t)b * HWm * 128;
        float4 c00 = ((const float4*)&g_P[base + (size_t)(y0 * w + x0) * 128])[lane];
        float4 c01 = ((const float4*)&g_P[base + (size_t)(y0 * w + x1) * 128])[lane];
        float4 c10 = ((const float4*)&g_P[base + (size_t)(y1 * w + x0) * 128])[lane];
        float4 c11 = ((const float4*)&g_P[base + (size_t)(y1 * w + x1) * 128])[lane];
        float w00 = wy0 * wx0, w01 = wy0 * wx1, w10 = wy1 * wx0, w11 = wy1 * wx1;
        acc.x += w00 * c00.x + w01 * c01.x + w10 * c10.x + w11 * c11.x;
        acc.y += w00 * c00.y + w01 * c01.y + w10 * c10.y + w11 * c11.y;
        acc.z += w00 * c00.z + w01 * c01.z + w10 * c10.z + w11 * c11.z;
        acc.w += w00 * c00.w + w01 * c01.w + w10 * c10.w + w11 * c11.w;
    }
    float4 bb = ((const float4*)bias)[lane];
    acc.x = fmaxf(acc.x + bb.x, 0.f);
    acc.y = fmaxf(acc.y + bb.y, 0.f);
    acc.z = fmaxf(acc.z + bb.z, 0.f);
    acc.w = fmaxf(acc.w + bb.w, 0.f);
    float* row = &g_X0[(size_t)v * XSTR];
    ((float4*)row)[lane] = acc;
    if (lane < 3) row[128 + lane] = vp[(size_t)v * 3 + lane];
#pragma unroll
    for (int j = 0; j < 8; j++)
        row[131 + lane * 8 + j] = enc[(size_t)b * 256 + lane * 8 + j];
}

// =========================================================================
// CSR build (edges are INT32)
// =========================================================================
__global__ void hist_kernel(const int* __restrict__ edges, int E)
{
    int i = blockIdx.x * blockDim.x + threadIdx.x;
    if (i >= E) return;
    atomicAdd(&g_cnt[edges[2 * i]], 1);
    atomicAdd(&g_cnt[edges[2 * i + 1]], 1);
}

__global__ void scan_kernel()
{
    __shared__ int part[1024];
    const int n = NV;
    int t = threadIdx.x;
    int chunk = (n + 1023) >> 10;
    int base = t * chunk;
    int sum = 0;
    for (int j = 0; j < chunk; j++) {
        int idx = base + j;
        if (idx < n) sum += g_cnt[idx];
    }
    part[t] = sum;
    __syncthreads();
    for (int off = 1; off < 1024; off <<= 1) {
        int v = 0;
        if (t >= off) v = part[t - off];
        __syncthreads();
        part[t] += v;
        __syncthreads();
    }
    int run = part[t] - sum;
    for (int j = 0; j < chunk; j++) {
        int idx = base + j;
        if (idx < n) { g_offs[idx] = run; run += g_cnt[idx]; }
    }
    if (t == 1023) g_offs[n] = part[1023];
}

__global__ void fill_kernel(const int* __restrict__ edges, int E)
{
    int i = blockIdx.x * blockDim.x + threadIdx.x;
    if (i >= E) return;
    int v0 = edges[2 * i];
    int v1 = edges[2 * i + 1];
    int p0 = atomicAdd(&g_cnt[v0], 1);
    g_entries[g_offs[v0] + p0] = v1;
    int p1 = atomicAdd(&g_cnt[v1], 1);
    g_entries[g_offs[v1] + p1] = v0;
}

// =========================================================================
// fp16x3 dual GEMM with FUSED graph gather in A-staging:
//   x[v] = (layer0) X0[v]   |   relu(H0prev[v] + sum_nb H1prev[nb])
//   H0 = x@W0+b0 ; H1out = x@W1+b1
// BM=128, BN=256, K chunked by 32, double-buffered staging.
// xsel: 0=g_X0 (no gather), 1=g_bufA, 2=g_bufB (gather+relu, h1sel names prev H1)
// =========================================================================
#define BUFW 12288                       // words per buffer
#define SMEM_GEMM_BYTES (2 * BUFW * 4)   // 96 KB

__global__ void __launch_bounds__(512, 1) gemm_f16x3(
    int xsel, int h1sel, int Kin, int img0,
    const float* __restrict__ b0, const float* __restrict__ b1,
    int oselH0, int oselH1)
{
    extern __shared__ uint32_t smw[];

    const float* X    = (xsel == 0) ? g_X0 : (xsel == 1) ? g_bufA : g_bufB;
    const float* H1p  = (h1sel == 1) ? g_H1 : g_H2;
    int ldx = (xsel == 0) ? XSTR : 128;
    int gat = (xsel != 0);
    float* H0out = (oselH0 == 1) ? g_bufA : g_bufB;
    float* H1out = (oselH1 == 1) ? g_H1 : g_H2;

    int tid = threadIdx.x;
    int lane = tid & 31;
    int wid = tid >> 5;
    int warp_m = wid >> 3;    // 0..1
    int warp_n = wid & 7;     // 0..7
    int row0 = blockIdx.x * 128;

    float d[4][4][4];
#pragma unroll
    for (int mt = 0; mt < 4; mt++)
#pragma unroll
        for (int nt = 0; nt < 4; nt++)
#pragma unroll
            for (int q = 0; q < 4; q++) d[mt][nt][q] = 0.f;

    int nch = (Kin + 31) >> 5;

    // staging: chunk c -> buffer buf (0/1)
    auto stage = [&](int c, int buf) {
        uint32_t* sAh = smw + buf * BUFW;
        uint32_t* sAl = sAh + 2048;
        uint32_t* sBh = sAh + 4096;
        uint32_t* sBl = sAh + 8192;
        int kc = c * 32;
        int kmax = min(32, Kin - kc);
        // B copy (prepacked fragments)
        const uint4* src = (const uint4*)&g_pack[(size_t)(img0 + c) * 8192];
#pragma unroll
        for (int i = 0; i < 4; i++) {
            int idx = tid + i * 512;       // 0..2047 uint4
            uint4 v = src[idx];
            if (idx < 1024) ((uint4*)sBh)[idx] = v;
            else            ((uint4*)sBl)[idx - 1024] = v;
        }
        // A stage: thread owns (row r, 8-k segment cs)
        int r  = tid >> 2;
        int cs = tid & 3;
        int grow = row0 + r;
        int cbase = cs * 8;
        float vv[8] = {0.f, 0.f, 0.f, 0.f, 0.f, 0.f, 0.f, 0.f};
        if (grow < NV) {
            if (gat) {
                const float* rowp = &X[(size_t)grow * 128 + kc + cbase];
                float4 a0 = *(const float4*)&rowp[0];
                float4 a1 = *(const float4*)&rowp[4];
                vv[0] = a0.x; vv[1] = a0.y; vv[2] = a0.z; vv[3] = a0.w;
                vv[4] = a1.x; vv[5] = a1.y; vv[6] = a1.z; vv[7] = a1.w;
                int s = g_offs[grow], e = g_offs[grow + 1];
                for (int i = s; i < e; i++) {
                    int nb = g_entries[i];
                    const float* np = &H1p[(size_t)nb * 128 + kc + cbase];
                    float4 h0v = *(const float4*)&np[0];
                    float4 h1v = *(const float4*)&np[4];
                    vv[0] += h0v.x; vv[1] += h0v.y; vv[2] += h0v.z; vv[3] += h0v.w;
                    vv[4] += h1v.x; vv[5] += h1v.y; vv[6] += h1v.z; vv[7] += h1v.w;
                }
#pragma unroll
                for (int j = 0; j < 8; j++) vv[j] = fmaxf(vv[j], 0.f);
            } else {
                if (cbase + 8 <= kmax) {
                    float4 p0v = *(const float4*)&X[(size_t)grow * ldx + kc + cbase];
                    float4 p1v = *(const float4*)&X[(size_t)grow * ldx + kc + cbase + 4];
                    vv[0] = p0v.x; vv[1] = p0v.y; vv[2] = p0v.z; vv[3] = p0v.w;
                    vv[4] = p1v.x; vv[5] = p1v.y; vv[6] = p1v.z; vv[7] = p1v.w;
                } else {
#pragma unroll
                    for (int j = 0; j < 8; j++) {
                        int kk = cbase + j;
                        if (kk < kmax) vv[j] = X[(size_t)grow * ldx + kc + kk];
                    }
                }
            }
        }
        __half hh[8], ll[8];
#pragma unroll
        for (int j = 0; j < 8; j++) {
            float x = vv[j];
            __half hi = __float2half_rn(x);
            hh[j] = hi;
            ll[j] = __float2half_rn(x - __half2float(hi));
        }
        int rr = r & 15;
        int blk = (r >> 4) * 2 + (cs >> 1);
        int rg  = (cs & 1) * 2 + ((rr >= 8) ? 1 : 0);
        int wbase = blk * 128 + (rr & 7) * 16 + rg;
#pragma unroll
        for (int t = 0; t < 4; t++) {
            sAh[wbase + t * 4] = pack_h2(hh[2 * t], hh[2 * t + 1]);
            sAl[wbase + t * 4] = pack_h2(ll[2 * t], ll[2 * t + 1]);
        }
    };

    stage(0, 0);
    __syncthreads();

    for (int c = 0; c < nch; c++) {
        int buf = c & 1;
        if (c + 1 < nch) stage(c + 1, buf ^ 1);

        uint32_t* sAh = smw + buf * BUFW;
        uint32_t* sAl = sAh + 2048;
        uint32_t* sBh = sAh + 4096;
        uint32_t* sBl = sAh + 8192;
#pragma unroll
        for (int ks = 0; ks < 2; ks++) {
            uint32_t bh[4][2], bl[4][2];
#pragma unroll
            for (int nt = 0; nt < 4; nt++) {
                int Ni = warp_n * 4 + nt;
                int w = ((Ni * 2 + ks) * 32 + lane) * 2;
                uint2 th = *(const uint2*)&sBh[w];
                uint2 tl = *(const uint2*)&sBl[w];
                bh[nt][0] = th.x; bh[nt][1] = th.y;
                bl[nt][0] = tl.x; bl[nt][1] = tl.y;
            }
#pragma unroll
            for (int mt = 0; mt < 4; mt++) {
                int Mi = warp_m * 4 + mt;
                int w = ((Mi * 2 + ks) * 32 + lane) * 4;
                uint4 th = *(const uint4*)&sAh[w];
                uint4 tl = *(const uint4*)&sAl[w];
                uint32_t ah[4] = {th.x, th.y, th.z, th.w};
                uint32_t al[4] = {tl.x, tl.y, tl.z, tl.w};
#pragma unroll
                for (int nt = 0; nt < 4; nt++) {
                    mma_f16(d[mt][nt], ah, bl[nt]);
                    mma_f16(d[mt][nt], al, bh[nt]);
                    mma_f16(d[mt][nt], ah, bh[nt]);
                }
            }
        }
        __syncthreads();
    }
    // ---- epilogue ----
#pragma unroll
    for (int nt = 0; nt < 4; nt++) {
        int gcol = warp_n * 32 + nt * 8;
        float* Hout; const float* bias; int cb;
        if (gcol < 128) { Hout = H0out; bias = b0; cb = gcol; }
        else            { Hout = H1out; bias = b1; cb = gcol - 128; }
        int c0 = cb + (lane & 3) * 2;
        float2 bv = *(const float2*)&bias[c0];
#pragma unroll
        for (int mt = 0; mt < 4; mt++) {
            int rtop = row0 + warp_m * 64 + mt * 16 + (lane >> 2);
            if (rtop < NV) {
                float2 o = make_float2(d[mt][nt][0] + bv.x, d[mt][nt][1] + bv.y);
                *(float2*)&Hout[(size_t)rtop * 128 + c0] = o;
            }
            int rbot = rtop + 8;
            if (rbot < NV) {
                float2 o = make_float2(d[mt][nt][2] + bv.x, d[mt][nt][3] + bv.y);
                *(float2*)&Hout[(size_t)rbot * 128 + c0] = o;
            }
        }
    }
}

// =========================================================================
// Final projection with fused gather:
//   x = relu(H0[v] + sum_nb H1[nb]);  out = x @ off_w + off_b  (128 -> 3)
// =========================================================================
__global__ void final_kernel(int xsel, int h1sel,
                             const float* __restrict__ ow, const float* __restrict__ ob,
                             float* __restrict__ out)
{
    const float* X   = (xsel == 1) ? g_bufA : g_bufB;
    const float* H1p = (h1sel == 1) ? g_H1 : g_H2;
    int gwarp = (blockIdx.x * blockDim.x + threadIdx.x) >> 5;
    int lane = threadIdx.x & 31;
    if (gwarp >= NV) return;
    int v = gwarp;
    float4 x = ((const float4*)&X[(size_t)v * 128])[lane];
    int s = g_offs[v], e = g_offs[v + 1];
    for (int i = s; i < e; i++) {
        int nb = g_entries[i];
        float4 h = ((const float4*)&H1p[(size_t)nb * 128])[lane];
        x.x += h.x; x.y += h.y; x.z += h.z; x.w += h.w;
    }
    x.x = fmaxf(x.x, 0.f); x.y = fmaxf(x.y, 0.f);
    x.z = fmaxf(x.z, 0.f); x.w = fmaxf(x.w, 0.f);
    const float* wr = &ow[(size_t)(lane * 4) * 3];
    float s0 = x.x * wr[0] + x.y * wr[3] + x.z * wr[6] + x.w * wr[9];
    float s1 = x.x * wr[1] + x.y * wr[4] + x.z * wr[7] + x.w * wr[10];
    float s2 = x.x * wr[2] + x.y * wr[5] + x.z * wr[8] + x.w * wr[11];
#pragma unroll
    for (int o = 16; o > 0; o >>= 1) {
        s0 += __shfl_down_sync(0xffffffffu, s0, o);
        s1 += __shfl_down_sync(0xffffffffu, s1, o);
        s2 += __shfl_down_sync(0xffffffffu, s2, o);
    }
    if (lane == 0) {
        out[(size_t)v * 3 + 0] = s0 + ob[0];
        out[(size_t)v * 3 + 1] = s1 + ob[1];
        out[(size_t)v * 3 + 2] = s2 + ob[2];
    }
}

// =========================================================================
extern "C" void kernel_launch(void* const* d_in, const int* in_sizes, int n_in,
                              void* d_out, int out_size)
{
    const float* f1   = (const float*)d_in[0];
    const float* f2   = (const float*)d_in[1];
    const float* f3   = (const float*)d_in[2];
    const float* f4   = (const float*)d_in[3];
    const float* av   = (const float*)d_in[4];
    const float* vp   = (const float*)d_in[5];
    const float* enc  = (const float*)d_in[6];
    const int*   edges = (const int*)d_in[7];
    const float* bw   = (const float*)d_in[8];
    const float* bb   = (const float*)d_in[9];
    const float* g0w0 = (const float*)d_in[10];
    const float* g0b0 = (const float*)d_in[11];
    const float* g0w1 = (const float*)d_in[12];
    const float* g0b1 = (const float*)d_in[13];
    const float* gw0  = (const float*)d_in[14];
    const float* gb0  = (const float*)d_in[15];
    const float* gw1  = (const float*)d_in[16];
    const float* gb1  = (const float*)d_in[17];
    const float* ow   = (const float*)d_in[18];
    const float* ob   = (const float*)d_in[19];
    float* out = (float*)d_out;

    int E = in_sizes[7] / 2;

    cudaFuncSetAttribute(gemm_f16x3,
                         cudaFuncAttributeMaxDynamicSharedMemorySize,
                         SMEM_GEMM_BYTES);

    const int WARP_GRID = (NV + 7) / 8;
    const int GEMM_GRID = (NV + 127) / 128;   // 321

    // weight prepack (one pass; independent of activations)
    prepack_weights<<<(NIMG * 4096 + 255) / 256, 256>>>(g0w0, g0w1, gw0, gw1);

    // P projection tables (split-K -> zero first)
    zero_P_kernel<<<(PTOT / 4 + 255) / 256, 256>>>();
    precompute_kernel<<<396, 128>>>(f1, f2, f3, f4, bw);
    sampler_kernel<<<WARP_GRID, 256>>>(av, vp, enc, bb);

    // CSR build
    zero_cnt_kernel<<<(NV + 255) / 256, 256>>>();
    hist_kernel<<<(E + 255) / 256, 256>>>(edges, E);
    scan_kernel<<<1, 1024>>>();
    zero_cnt_kernel<<<(NV + 255) / 256, 256>>>();
    fill_kernel<<<(E + 255) / 256, 256>>>(edges, E);

    // layer 0 (Kin=387, from X0, no gather): H0 -> bufA, H1 -> g_H1
    gemm_f16x3<<<GEMM_GRID, 512, SMEM_GEMM_BYTES>>>(0, 1, 387, 0,
                                                    g0b0, g0b1, 1, 1);

    // layers 1..7: fused gather of (H0prev, H1prev), ping-pong both buffers
    int curH0 = 1, curH1 = 1;
    for (int i = 0; i < 7; i++) {
        int nxtH0 = 3 - curH0, nxtH1 = 3 - curH1;
        int img0 = 13 + i * 4;
        gemm_f16x3<<<GEMM_GRID, 512, SMEM_GEMM_BYTES>>>(curH0, curH1, 128, img0,
                                       gb0 + (size_t)i * 128,
                                       gb1 + (size_t)i * 128,
                                       nxtH0, nxtH1);
        curH0 = nxtH0; curH1 = nxtH1;
    }

    // final: fused gather + relu + projection
    final_kernel<<<WARP_GRID, 256>>>(curH0, curH1, ow, ob, out);
}

// round 12
// speedup vs baseline: 1.1103x; 1.1103x over previous
#include <cuda_runtime.h>
#include <cuda_bf16.h>
#include <cuda_fp16.h>
#include <cstdint>

#define NV   40968           // total vertices (B*V)
#define VPER 10242
#define XSTR 392             // padded row stride of X0 (387 used)
#define PTOT 2132480         // total floats in P tables

// P table offsets (floats) per feature map: B*HW*128 cumulative
#define POFF0 0
#define POFF1 1605632
#define POFF2 2007040
#define POFF3 2107392

// weight images: 41 images (layer0: 13 chunks, layers1-7: 4 each), each
// 8192 uint32 words (hi 4096 | lo 4096) in mma fragment layout.
#define NIMG 41
#define NTILES 321            // ceil(NV/128)

// ---------------- device scratch (module globals; no allocations) --------
__device__ float g_P[PTOT];
__device__ float g_X0[(size_t)NV * XSTR];
__device__ float g_bufA[(size_t)NV * 128];
__device__ float g_bufB[(size_t)NV * 128];
__device__ float g_H1[(size_t)NV * 128];
__device__ int   g_cnt[NV];
__device__ int   g_offs[NV + 1];
__device__ int   g_entries[245760];
__device__ __align__(16) uint32_t g_pack[NIMG * 8192];
__device__ int   g_tctr[8];          // per-GEMM-launch tile counters

// ---------------- f32x2 helpers (precompute kernel) ----------------
__device__ __forceinline__ unsigned long long dup2(float x) {
    unsigned long long r;
    asm("mov.b64 %0, {%1, %1};" : "=l"(r) : "f"(x));
    return r;
}
__device__ __forceinline__ void ffma2(unsigned long long &d, unsigned long long a, unsigned long long b) {
    asm("fma.rn.f32x2 %0, %1, %2, %0;" : "+l"(d) : "l"(a), "l"(b));
}
__device__ __forceinline__ float2 unpk(unsigned long long v) {
    float2 r;
    asm("mov.b64 {%0, %1}, %2;" : "=f"(r.x), "=f"(r.y) : "l"(v));
    return r;
}

// fp16 mma m16n8k16, f32 accumulate
__device__ __forceinline__ void mma_f16(float* d, const uint32_t* a, const uint32_t* b) {
    asm("mma.sync.aligned.m16n8k16.row.col.f32.f16.f16.f32 "
        "{%0,%1,%2,%3},{%4,%5,%6,%7},{%8,%9},{%0,%1,%2,%3};"
        : "+f"(d[0]), "+f"(d[1]), "+f"(d[2]), "+f"(d[3])
        : "r"(a[0]), "r"(a[1]), "r"(a[2]), "r"(a[3]), "r"(b[0]), "r"(b[1]));
}
__device__ __forceinline__ uint32_t pack_h2(__half a, __half b) {
    __half2 h2 = __halves2half2(a, b);
    return *(uint32_t*)&h2;
}

// =========================================================================
// zero kernels  (also clears the GEMM tile counters)
// =========================================================================
__global__ void zero_cnt_kernel()
{
    int i = blockIdx.x * blockDim.x + threadIdx.x;
    if (i < NV) g_cnt[i] = 0;
    if (blockIdx.x == 0 && threadIdx.x < 8) g_tctr[threadIdx.x] = 0;
}
__global__ void zero_P_kernel()
{
    int i = blockIdx.x * blockDim.x + threadIdx.x;
    if (i < PTOT / 4) ((float4*)g_P)[i] = make_float4(0.f, 0.f, 0.f, 0.f);
}

// =========================================================================
// Weight prepack -> fragment-layout hi/lo fp16 images.
// =========================================================================
__global__ void prepack_weights(
    const float* __restrict__ g0w0, const float* __restrict__ g0w1,
    const float* __restrict__ gw0,  const float* __restrict__ gw1)
{
    int idx = blockIdx.x * 256 + threadIdx.x;
    if (idx >= NIMG * 4096) return;
    int img = idx >> 12;
    int e   = idx & 4095;
    int n   = e >> 4;          // 0..255
    int kp  = e & 15;          // k-pair 0..15 (k = 2*kp)

    const float *W0, *W1; int Kin, chunk;
    if (img < 13) { W0 = g0w0; W1 = g0w1; Kin = 387; chunk = img; }
    else {
        int t = img - 13;
        int L = t >> 2; chunk = t & 3;
        W0 = gw0 + (size_t)L * 16384;
        W1 = gw1 + (size_t)L * 16384;
        Kin = 128;
    }
    const float* W = (n < 128) ? W0 : W1;
    int col = n & 127;
    int kg = chunk * 32 + kp * 2;
    float w0v = (kg     < Kin) ? W[(size_t)kg * 128 + col]       : 0.f;
    float w1v = (kg + 1 < Kin) ? W[(size_t)(kg + 1) * 128 + col] : 0.f;

    __half h0 = __float2half_rn(w0v);
    __half l0 = __float2half_rn(w0v - __half2float(h0));
    __half h1 = __float2half_rn(w1v);
    __half l1 = __float2half_rn(w1v - __half2float(h1));

    int Ni = n >> 3, nn = n & 7;
    int kk = kp * 2;
    int Ks = kk >> 4;
    int kk16 = kk & 15;
    int rg = (kk16 >= 8) ? 1 : 0;
    int t  = (kk16 & 7) >> 1;
    int word = ((Ni * 2 + Ks) * 32 + nn * 4 + t) * 2 + rg;
    size_t base = (size_t)img * 8192;
    g_pack[base + word]        = pack_h2(h0, h1);
    g_pack[base + 4096 + word] = pack_h2(l0, l1);
}

// =========================================================================
// Kernel 1: per-pixel projection, split-K balanced, atomicAdd epilogue.
// =========================================================================
__global__ void __launch_bounds__(128) precompute_kernel(
    const float* __restrict__ f1, const float* __restrict__ f2,
    const float* __restrict__ f3, const float* __restrict__ f4,
    const float* __restrict__ BW)
{
    __shared__ float As[32][68];
    __shared__ float Bs[32][128];

    int bid = blockIdx.x;
    int m, local;
    if (bid < 196)      { m = 0; local = bid; }
    else if (bid < 300) { m = 1; local = bid - 196; }
    else if (bid < 364) { m = 2; local = bid - 300; }
    else                { m = 3; local = bid - 364; }

    const float* fm;
    int HW, C, WO, ks; size_t poff;
    if (m == 0)      { fm = f1; HW = 3136; C = 256;  WO = 0;    poff = POFF0; ks = 1; }
    else if (m == 1) { fm = f2; HW = 784;  C = 512;  WO = 256;  poff = POFF1; ks = 2; }
    else if (m == 2) { fm = f3; HW = 196;  C = 1024; WO = 768;  poff = POFF2; ks = 4; }
    else             { fm = f4; HW = 49;   C = 2048; WO = 1792; poff = POFF3; ks = 8; }

    int kt   = local % ks;
    int rest = local / ks;
    int b  = rest & 3;
    int mt = rest >> 2;

    int p0  = mt * 64;
    int kc0 = kt * 256;
    int tid = threadIdx.x;
    int rowg = tid & 7;
    int colg = tid >> 3;
    int r0 = rowg * 8;
    int c0 = colg * 8;

    unsigned long long acc[8][4];
#pragma unroll
    for (int i = 0; i < 8; i++)
#pragma unroll
        for (int j = 0; j < 4; j++) acc[i][j] = 0ULL;

    for (int ch = 0; ch < 8; ch++) {
        int kk = kc0 + ch * 32;
#pragma unroll
        for (int i = 0; i < 16; i++) {
            int lin = tid + i * 128;
            int c = lin >> 6;
            int p = lin & 63;
            float v = 0.f;
            if (p0 + p < HW)
                v = fm[((size_t)b * C + (kk + c)) * HW + p0 + p];
            As[c][p] = v;
        }
#pragma unroll
        for (int i = 0; i < 8; i++) {
            int lin4 = tid + i * 128;
            int k = lin4 >> 5;
            int n4 = (lin4 & 31) * 4;
            float4 v = *(const float4*)&BW[(size_t)(WO + kk + k) * 128 + n4];
            *(float4*)&Bs[k][n4] = v;
        }
        __syncthreads();
#pragma unroll 2
        for (int k = 0; k < 32; k++) {
            float4 aA = *(const float4*)&As[k][r0];
            float4 aB = *(const float4*)&As[k][r0 + 4];
            unsigned long long ad[8] = {dup2(aA.x), dup2(aA.y), dup2(aA.z), dup2(aA.w),
                                        dup2(aB.x), dup2(aB.y), dup2(aB.z), dup2(aB.w)};
            ulonglong2 bp0 = *(const ulonglong2*)&Bs[k][c0];
            ulonglong2 bp1 = *(const ulonglong2*)&Bs[k][c0 + 4];
            unsigned long long bb[4] = {bp0.x, bp0.y, bp1.x, bp1.y};
#pragma unroll
            for (int i = 0; i < 8; i++)
#pragma unroll
                for (int j = 0; j < 4; j++) ffma2(acc[i][j], ad[i], bb[j]);
        }
        __syncthreads();
    }
    size_t pbase = poff + (size_t)b * HW * 128;
#pragma unroll
    for (int i = 0; i < 8; i++) {
        int pix = p0 + r0 + i;
        if (pix >= HW) continue;
        float* dst = &g_P[pbase + (size_t)pix * 128 + c0];
        if (ks == 1) {
#pragma unroll
            for (int j = 0; j < 2; j++) {
                float2 vA = unpk(acc[i][j * 2]);
                float2 vB = unpk(acc[i][j * 2 + 1]);
                *(float4*)&dst[j * 4] = make_float4(vA.x, vA.y, vB.x, vB.y);
            }
        } else {
#pragma unroll
            for (int j = 0; j < 4; j++) {
                float2 v = unpk(acc[i][j]);
                atomicAdd(&dst[j * 2 + 0], v.x);
                atomicAdd(&dst[j * 2 + 1], v.y);
            }
        }
    }
}

// =========================================================================
// Kernel 2: bilinear sampler + bias + relu + assemble X0 row
// =========================================================================
__global__ void sampler_kernel(
    const float* __restrict__ av, const float* __restrict__ vp,
    const float* __restrict__ enc, const float* __restrict__ bias)
{
    int gwarp = (blockIdx.x * blockDim.x + threadIdx.x) >> 5;
    int lane = threadIdx.x & 31;
    if (gwarp >= NV) return;
    int v = gwarp;
    int b = v / VPER;

    float gx = av[(size_t)v * 3 + 0];
    float gy = av[(size_t)v * 3 + 1];

    float4 acc = make_float4(0.f, 0.f, 0.f, 0.f);
#pragma unroll
    for (int m = 0; m < 4; m++) {
        const int DIMm = (m == 0) ? 56 : (m == 1) ? 28 : (m == 2) ? 14 : 7;
        const int HWm  = DIMm * DIMm;
        const size_t POm = (m == 0) ? POFF0 : (m == 1) ? POFF1 : (m == 2) ? POFF2 : POFF3;
        int w = DIMm;
        float fx = (gx + 1.f) * 0.5f * (float)(w - 1);
        float fy = (gy + 1.f) * 0.5f * (float)(w - 1);
        float x0f = floorf(fx), y0f = floorf(fy);
        float wx1 = fx - x0f, wy1 = fy - y0f;
        float wx0 = 1.f - wx1, wy0 = 1.f - wy1;
        int x0 = min(max((int)x0f, 0), w - 1);
        int x1 = min(max((int)x0f + 1, 0), w - 1);
        int y0 = min(max((int)y0f, 0), w - 1);
        int y1 = min(max((int)y0f + 1, 0), w - 1);
        size_t base = POm + (size_t)b * HWm * 128;
        float4 c00 = ((const float4*)&g_P[base + (size_t)(y0 * w + x0) * 128])[lane];
        float4 c01 = ((const float4*)&g_P[base + (size_t)(y0 * w + x1) * 128])[lane];
        float4 c10 = ((const float4*)&g_P[base + (size_t)(y1 * w + x0) * 128])[lane];
        float4 c11 = ((const float4*)&g_P[base + (size_t)(y1 * w + x1) * 128])[lane];
        float w00 = wy0 * wx0, w01 = wy0 * wx1, w10 = wy1 * wx0, w11 = wy1 * wx1;
        acc.x += w00 * c00.x + w01 * c01.x + w10 * c10.x + w11 * c11.x;
        acc.y += w00 * c00.y + w01 * c01.y + w10 * c10.y + w11 * c11.y;
        acc.z += w00 * c00.z + w01 * c01.z + w10 * c10.z + w11 * c11.z;
        acc.w += w00 * c00.w + w01 * c01.w + w10 * c10.w + w11 * c11.w;
    }
    float4 bb = ((const float4*)bias)[lane];
    acc.x = fmaxf(acc.x + bb.x, 0.f);
    acc.y = fmaxf(acc.y + bb.y, 0.f);
    acc.z = fmaxf(acc.z + bb.z, 0.f);
    acc.w = fmaxf(acc.w + bb.w, 0.f);
    float* row = &g_X0[(size_t)v * XSTR];
    ((float4*)row)[lane] = acc;
    if (lane < 3) row[128 + lane] = vp[(size_t)v * 3 + lane];
#pragma unroll
    for (int j = 0; j < 8; j++)
        row[131 + lane * 8 + j] = enc[(size_t)b * 256 + lane * 8 + j];
}

// =========================================================================
// CSR build (edges are INT32)
// =========================================================================
__global__ void hist_kernel(const int* __restrict__ edges, int E)
{
    int i = blockIdx.x * blockDim.x + threadIdx.x;
    if (i >= E) return;
    atomicAdd(&g_cnt[edges[2 * i]], 1);
    atomicAdd(&g_cnt[edges[2 * i + 1]], 1);
}

__global__ void scan_kernel()
{
    __shared__ int part[1024];
    const int n = NV;
    int t = threadIdx.x;
    int chunk = (n + 1023) >> 10;
    int base = t * chunk;
    int sum = 0;
    for (int j = 0; j < chunk; j++) {
        int idx = base + j;
        if (idx < n) sum += g_cnt[idx];
    }
    part[t] = sum;
    __syncthreads();
    for (int off = 1; off < 1024; off <<= 1) {
        int v = 0;
        if (t >= off) v = part[t - off];
        __syncthreads();
        part[t] += v;
        __syncthreads();
    }
    int run = part[t] - sum;
    for (int j = 0; j < chunk; j++) {
        int idx = base + j;
        if (idx < n) { g_offs[idx] = run; run += g_cnt[idx]; }
    }
    if (t == 1023) g_offs[n] = part[1023];
}

__global__ void fill_kernel(const int* __restrict__ edges, int E)
{
    int i = blockIdx.x * blockDim.x + threadIdx.x;
    if (i >= E) return;
    int v0 = edges[2 * i];
    int v1 = edges[2 * i + 1];
    int p0 = atomicAdd(&g_cnt[v0], 1);
    g_entries[g_offs[v0] + p0] = v1;
    int p1 = atomicAdd(&g_cnt[v1], 1);
    g_entries[g_offs[v1] + p1] = v0;
}

// =========================================================================
// PERSISTENT fp16x3 dual GEMM via mma.m16n8k16 + atomic tile queue:
//   H0 = act(X)@W0+b0 ; g_H1 = act(X)@W1+b1
// Grid = 152 persistent blocks; tiles (128 rows each) popped from g_tctr[cid].
// Per tile: BM=128, BN=256, K chunked by 32, double-buffered staging.
// =========================================================================
#define BUFW 12288                       // words per buffer
#define SMEM_GEMM_BYTES (2 * BUFW * 4)   // 96 KB

__global__ void __launch_bounds__(512, 1) gemm_f16x3(
    int xsel, int Kin, int reluIn, int img0, int cid,
    const float* __restrict__ b0, const float* __restrict__ b1,
    int osel)
{
    extern __shared__ uint32_t smw[];
    __shared__ int s_tile;

    const float* X = (xsel == 0) ? g_X0 : (xsel == 1) ? g_bufA : g_bufB;
    int ldx = (xsel == 0) ? XSTR : 128;
    float* H0 = (osel == 1) ? g_bufA : g_bufB;

    int tid = threadIdx.x;
    int lane = tid & 31;
    int wid = tid >> 5;
    int warp_m = wid >> 3;    // 0..1
    int warp_n = wid & 7;     // 0..7

    int nch = (Kin + 31) >> 5;

    while (true) {
        if (tid == 0) s_tile = atomicAdd(&g_tctr[cid], 1);
        __syncthreads();
        int tile = s_tile;
        __syncthreads();          // all read s_tile before next overwrite
        if (tile >= NTILES) break;
        int row0 = tile * 128;

        float d[4][4][4];
#pragma unroll
        for (int mt = 0; mt < 4; mt++)
#pragma unroll
            for (int nt = 0; nt < 4; nt++)
#pragma unroll
                for (int q = 0; q < 4; q++) d[mt][nt][q] = 0.f;

        // staging: chunk c -> buffer buf (0/1)
        auto stage = [&](int c, int buf) {
            uint32_t* sAh = smw + buf * BUFW;
            uint32_t* sAl = sAh + 2048;
            uint32_t* sBh = sAh + 4096;
            uint32_t* sBl = sAh + 8192;
            int kc = c * 32;
            int kmax = min(32, Kin - kc);
            const uint4* src = (const uint4*)&g_pack[(size_t)(img0 + c) * 8192];
#pragma unroll
            for (int i = 0; i < 4; i++) {
                int idx = tid + i * 512;
                uint4 v = src[idx];
                if (idx < 1024) ((uint4*)sBh)[idx] = v;
                else            ((uint4*)sBl)[idx - 1024] = v;
            }
            int r  = tid >> 2;
            int cs = tid & 3;
            int grow = row0 + r;
            float vv[8];
            int cbase = cs * 8;
            if (grow < NV && cbase + 8 <= kmax) {
                float4 p0v = *(const float4*)&X[(size_t)grow * ldx + kc + cbase];
                float4 p1v = *(const float4*)&X[(size_t)grow * ldx + kc + cbase + 4];
                vv[0] = p0v.x; vv[1] = p0v.y; vv[2] = p0v.z; vv[3] = p0v.w;
                vv[4] = p1v.x; vv[5] = p1v.y; vv[6] = p1v.z; vv[7] = p1v.w;
            } else {
#pragma unroll
                for (int j = 0; j < 8; j++) {
                    int kk = cbase + j;
                    vv[j] = (grow < NV && kk < kmax)
                          ? X[(size_t)grow * ldx + kc + kk] : 0.f;
                }
            }
            __half hh[8], ll[8];
#pragma unroll
            for (int j = 0; j < 8; j++) {
                float x = vv[j];
                if (reluIn) x = fmaxf(x, 0.f);
                __half hi = __float2half_rn(x);
                hh[j] = hi;
                ll[j] = __float2half_rn(x - __half2float(hi));
            }
            int rr = r & 15;
            int blk = (r >> 4) * 2 + (cs >> 1);
            int rg  = (cs & 1) * 2 + ((rr >= 8) ? 1 : 0);
            int wbase = blk * 128 + (rr & 7) * 16 + rg;
#pragma unroll
            for (int t = 0; t < 4; t++) {
                sAh[wbase + t * 4] = pack_h2(hh[2 * t], hh[2 * t + 1]);
                sAl[wbase + t * 4] = pack_h2(ll[2 * t], ll[2 * t + 1]);
            }
        };

        stage(0, 0);
        __syncthreads();

        for (int c = 0; c < nch; c++) {
            int buf = c & 1;
            if (c + 1 < nch) stage(c + 1, buf ^ 1);

            uint32_t* sAh = smw + buf * BUFW;
            uint32_t* sAl = sAh + 2048;
            uint32_t* sBh = sAh + 4096;
            uint32_t* sBl = sAh + 8192;
#pragma unroll
            for (int ks = 0; ks < 2; ks++) {
                uint32_t bh[4][2], bl[4][2];
#pragma unroll
                for (int nt = 0; nt < 4; nt++) {
                    int Ni = warp_n * 4 + nt;
                    int w = ((Ni * 2 + ks) * 32 + lane) * 2;
                    uint2 th = *(const uint2*)&sBh[w];
                    uint2 tl = *(const uint2*)&sBl[w];
                    bh[nt][0] = th.x; bh[nt][1] = th.y;
                    bl[nt][0] = tl.x; bl[nt][1] = tl.y;
                }
#pragma unroll
                for (int mt = 0; mt < 4; mt++) {
                    int Mi = warp_m * 4 + mt;
                    int w = ((Mi * 2 + ks) * 32 + lane) * 4;
                    uint4 th = *(const uint4*)&sAh[w];
                    uint4 tl = *(const uint4*)&sAl[w];
                    uint32_t ah[4] = {th.x, th.y, th.z, th.w};
                    uint32_t al[4] = {tl.x, tl.y, tl.z, tl.w};
#pragma unroll
                    for (int nt = 0; nt < 4; nt++) {
                        mma_f16(d[mt][nt], ah, bl[nt]);
                        mma_f16(d[mt][nt], al, bh[nt]);
                        mma_f16(d[mt][nt], ah, bh[nt]);
                    }
                }
            }
            __syncthreads();
        }
        // ---- epilogue ----
#pragma unroll
        for (int nt = 0; nt < 4; nt++) {
            int gcol = warp_n * 32 + nt * 8;
            float* Hout; const float* bias; int cb;
            if (gcol < 128) { Hout = H0;   bias = b0; cb = gcol; }
            else            { Hout = g_H1; bias = b1; cb = gcol - 128; }
            int c0 = cb + (lane & 3) * 2;
            float2 bv = *(const float2*)&bias[c0];
#pragma unroll
            for (int mt = 0; mt < 4; mt++) {
                int rtop = row0 + warp_m * 64 + mt * 16 + (lane >> 2);
                if (rtop < NV) {
                    float2 o = make_float2(d[mt][nt][0] + bv.x, d[mt][nt][1] + bv.y);
                    *(float2*)&Hout[(size_t)rtop * 128 + c0] = o;
                }
                int rbot = rtop + 8;
                if (rbot < NV) {
                    float2 o = make_float2(d[mt][nt][2] + bv.x, d[mt][nt][3] + bv.y);
                    *(float2*)&Hout[(size_t)rbot * 128 + c0] = o;
                }
            }
        }
        __syncthreads();   // smem reuse safety before next tile's staging
    }
}

// =========================================================================
// Gather: OUT[v] (holding h0) += sum_{nb in adj(v)} g_H1[nb]
// =========================================================================
__global__ void gather_kernel(int osel)
{
    float* OUT = (osel == 1) ? g_bufA : g_bufB;
    int gwarp = (blockIdx.x * blockDim.x + threadIdx.x) >> 5;
    int lane = threadIdx.x & 31;
    if (gwarp >= NV) return;
    int v = gwarp;
    int s = g_offs[v], e = g_offs[v + 1];
    float4 acc = ((const float4*)&OUT[(size_t)v * 128])[lane];
    int i = s;
    for (; i + 1 < e; i += 2) {
        int nb0 = g_entries[i];
        int nb1 = g_entries[i + 1];
        float4 h0 = ((const float4*)&g_H1[(size_t)nb0 * 128])[lane];
        float4 h1 = ((const float4*)&g_H1[(size_t)nb1 * 128])[lane];
        acc.x += h0.x + h1.x; acc.y += h0.y + h1.y;
        acc.z += h0.z + h1.z; acc.w += h0.w + h1.w;
    }
    if (i < e) {
        int nb = g_entries[i];
        float4 h = ((const float4*)&g_H1[(size_t)nb * 128])[lane];
        acc.x += h.x; acc.y += h.y; acc.z += h.z; acc.w += h.w;
    }
    ((float4*)&OUT[(size_t)v * 128])[lane] = acc;
}

// =========================================================================
// Final projection: out = relu(X) @ off_w + off_b   (128 -> 3)
// =========================================================================
__global__ void final_kernel(int xsel,
                             const float* __restrict__ ow, const float* __restrict__ ob,
                             float* __restrict__ out)
{
    const float* X = (xsel == 1) ? g_bufA : g_bufB;
    int gwarp = (blockIdx.x * blockDim.x + threadIdx.x) >> 5;
    int lane = threadIdx.x & 31;
    if (gwarp >= NV) return;
    int v = gwarp;
    float4 x = ((const float4*)&X[(size_t)v * 128])[lane];
    x.x = fmaxf(x.x, 0.f); x.y = fmaxf(x.y, 0.f);
    x.z = fmaxf(x.z, 0.f); x.w = fmaxf(x.w, 0.f);
    const float* wr = &ow[(size_t)(lane * 4) * 3];
    float s0 = x.x * wr[0] + x.y * wr[3] + x.z * wr[6] + x.w * wr[9];
    float s1 = x.x * wr[1] + x.y * wr[4] + x.z * wr[7] + x.w * wr[10];
    float s2 = x.x * wr[2] + x.y * wr[5] + x.z * wr[8] + x.w * wr[11];
#pragma unroll
    for (int o = 16; o > 0; o >>= 1) {
        s0 += __shfl_down_sync(0xffffffffu, s0, o);
        s1 += __shfl_down_sync(0xffffffffu, s1, o);
        s2 += __shfl_down_sync(0xffffffffu, s2, o);
    }
    if (lane == 0) {
        out[(size_t)v * 3 + 0] = s0 + ob[0];
        out[(size_t)v * 3 + 1] = s1 + ob[1];
        out[(size_t)v * 3 + 2] = s2 + ob[2];
    }
}

// =========================================================================
extern "C" void kernel_launch(void* const* d_in, const int* in_sizes, int n_in,
                              void* d_out, int out_size)
{
    const float* f1   = (const float*)d_in[0];
    const float* f2   = (const float*)d_in[1];
    const float* f3   = (const float*)d_in[2];
    const float* f4   = (const float*)d_in[3];
    const float* av   = (const float*)d_in[4];
    const float* vp   = (const float*)d_in[5];
    const float* enc  = (const float*)d_in[6];
    const int*   edges = (const int*)d_in[7];
    const float* bw   = (const float*)d_in[8];
    const float* bb   = (const float*)d_in[9];
    const float* g0w0 = (const float*)d_in[10];
    const float* g0b0 = (const float*)d_in[11];
    const float* g0w1 = (const float*)d_in[12];
    const float* g0b1 = (const float*)d_in[13];
    const float* gw0  = (const float*)d_in[14];
    const float* gb0  = (const float*)d_in[15];
    const float* gw1  = (const float*)d_in[16];
    const float* gb1  = (const float*)d_in[17];
    const float* ow   = (const float*)d_in[18];
    const float* ob   = (const float*)d_in[19];
    float* out = (float*)d_out;

    int E = in_sizes[7] / 2;

    cudaFuncSetAttribute(gemm_f16x3,
                         cudaFuncAttributeMaxDynamicSharedMemorySize,
                         SMEM_GEMM_BYTES);

    const int WARP_GRID = (NV + 7) / 8;
    const int PGRID = 152;    // persistent blocks (>= SM count)

    // weight prepack (one pass; independent of activations)
    prepack_weights<<<(NIMG * 4096 + 255) / 256, 256>>>(g0w0, g0w1, gw0, gw1);

    // P projection tables (split-K -> zero first)
    zero_P_kernel<<<(PTOT / 4 + 255) / 256, 256>>>();
    precompute_kernel<<<396, 128>>>(f1, f2, f3, f4, bw);
    sampler_kernel<<<WARP_GRID, 256>>>(av, vp, enc, bb);

    // CSR build (zero_cnt also clears the 8 GEMM tile counters)
    zero_cnt_kernel<<<(NV + 255) / 256, 256>>>();
    hist_kernel<<<(E + 255) / 256, 256>>>(edges, E);
    scan_kernel<<<1, 1024>>>();
    zero_cnt_kernel<<<(NV + 255) / 256, 256>>>();
    fill_kernel<<<(E + 255) / 256, 256>>>(edges, E);

    // layer 0 (Kin=387, no relu on input): images 0..12; H0 -> bufA
    gemm_f16x3<<<PGRID, 512, SMEM_GEMM_BYTES>>>(0, 387, 0, 0, 0, g0b0, g0b1, 1);
    gather_kernel<<<WARP_GRID, 256>>>(1);

    // layers 1..7 (Kin=128, relu on input), ping-pong bufA <-> bufB
    int cur = 1, nxt = 2;
    for (int i = 0; i < 7; i++) {
        int img0 = 13 + i * 4;
        gemm_f16x3<<<PGRID, 512, SMEM_GEMM_BYTES>>>(cur, 128, 1, img0, 1 + i,
                                       gb0 + (size_t)i * 128,
                                       gb1 + (size_t)i * 128,
                                       nxt);
        gather_kernel<<<WARP_GRID, 256>>>(nxt);
        int t = cur; cur = nxt; nxt = t;
    }

    final_kernel<<<WARP_GRID, 256>>>(cur, ow, ob, out);
}

// round 13
// speedup vs baseline: 1.1226x; 1.0111x over previous
#include <cuda_runtime.h>
#include <cuda_bf16.h>
#include <cuda_fp16.h>
#include <cstdint>

#define NV   40968           // total vertices (B*V)
#define VPER 10242
#define XSTR 392             // padded row stride of X0 (387 used)
#define PTOT 2132480         // total floats in P tables

// P table offsets (floats) per feature map: B*HW*128 cumulative
#define POFF0 0
#define POFF1 1605632
#define POFF2 2007040
#define POFF3 2107392

// weight images: 41 images (layer0: 13 chunks, layers1-7: 4 each), each
// 8192 uint32 words (hi 4096 | lo 4096) in mma fragment layout.
#define NIMG 41

// ---------------- device scratch (module globals; no allocations) --------
__device__ float g_P[PTOT];
__device__ float g_X0[(size_t)NV * XSTR];
__device__ float g_bufA[(size_t)NV * 128];
__device__ float g_bufB[(size_t)NV * 128];
__device__ float g_H1[(size_t)NV * 128];
__device__ int   g_cnt[NV];
__device__ int   g_offs[NV + 1];
__device__ int   g_entries[245760];
__device__ __align__(16) uint32_t g_pack[NIMG * 8192];

// ---------------- f32x2 helpers (precompute kernel) ----------------
__device__ __forceinline__ unsigned long long dup2(float x) {
    unsigned long long r;
    asm("mov.b64 %0, {%1, %1};" : "=l"(r) : "f"(x));
    return r;
}
__device__ __forceinline__ void ffma2(unsigned long long &d, unsigned long long a, unsigned long long b) {
    asm("fma.rn.f32x2 %0, %1, %2, %0;" : "+l"(d) : "l"(a), "l"(b));
}
__device__ __forceinline__ float2 unpk(unsigned long long v) {
    float2 r;
    asm("mov.b64 {%0, %1}, %2;" : "=f"(r.x), "=f"(r.y) : "l"(v));
    return r;
}

// fp16 mma m16n8k16, f32 accumulate
__device__ __forceinline__ void mma_f16(float* d, const uint32_t* a, const uint32_t* b) {
    asm("mma.sync.aligned.m16n8k16.row.col.f32.f16.f16.f32 "
        "{%0,%1,%2,%3},{%4,%5,%6,%7},{%8,%9},{%0,%1,%2,%3};"
        : "+f"(d[0]), "+f"(d[1]), "+f"(d[2]), "+f"(d[3])
        : "r"(a[0]), "r"(a[1]), "r"(a[2]), "r"(a[3]), "r"(b[0]), "r"(b[1]));
}
__device__ __forceinline__ uint32_t pack_h2(__half a, __half b) {
    __half2 h2 = __halves2half2(a, b);
    return *(uint32_t*)&h2;
}

// =========================================================================
// zero kernels
// =========================================================================
__global__ void zero_cnt_kernel()
{
    int i = blockIdx.x * blockDim.x + threadIdx.x;
    if (i < NV) g_cnt[i] = 0;
}
__global__ void zero_P_kernel()
{
    int i = blockIdx.x * blockDim.x + threadIdx.x;
    if (i < PTOT / 4) ((float4*)g_P)[i] = make_float4(0.f, 0.f, 0.f, 0.f);
}

// =========================================================================
// Weight prepack -> fragment-layout hi/lo fp16 images.
// =========================================================================
__global__ void prepack_weights(
    const float* __restrict__ g0w0, const float* __restrict__ g0w1,
    const float* __restrict__ gw0,  const float* __restrict__ gw1)
{
    int idx = blockIdx.x * 256 + threadIdx.x;
    if (idx >= NIMG * 4096) return;
    int img = idx >> 12;
    int e   = idx & 4095;
    int n   = e >> 4;          // 0..255
    int kp  = e & 15;          // k-pair 0..15 (k = 2*kp)

    const float *W0, *W1; int Kin, chunk;
    if (img < 13) { W0 = g0w0; W1 = g0w1; Kin = 387; chunk = img; }
    else {
        int t = img - 13;
        int L = t >> 2; chunk = t & 3;
        W0 = gw0 + (size_t)L * 16384;
        W1 = gw1 + (size_t)L * 16384;
        Kin = 128;
    }
    const float* W = (n < 128) ? W0 : W1;
    int col = n & 127;
    int kg = chunk * 32 + kp * 2;
    float w0v = (kg     < Kin) ? W[(size_t)kg * 128 + col]       : 0.f;
    float w1v = (kg + 1 < Kin) ? W[(size_t)(kg + 1) * 128 + col] : 0.f;

    __half h0 = __float2half_rn(w0v);
    __half l0 = __float2half_rn(w0v - __half2float(h0));
    __half h1 = __float2half_rn(w1v);
    __half l1 = __float2half_rn(w1v - __half2float(h1));

    int Ni = n >> 3, nn = n & 7;
    int kk = kp * 2;
    int Ks = kk >> 4;
    int kk16 = kk & 15;
    int rg = (kk16 >= 8) ? 1 : 0;
    int t  = (kk16 & 7) >> 1;
    int word = ((Ni * 2 + Ks) * 32 + nn * 4 + t) * 2 + rg;
    size_t base = (size_t)img * 8192;
    g_pack[base + word]        = pack_h2(h0, h1);
    g_pack[base + 4096 + word] = pack_h2(l0, l1);
}

// =========================================================================
// Kernel 1: per-pixel projection, split-K balanced, atomicAdd epilogue.
// =========================================================================
__global__ void __launch_bounds__(128) precompute_kernel(
    const float* __restrict__ f1, const float* __restrict__ f2,
    const float* __restrict__ f3, const float* __restrict__ f4,
    const float* __restrict__ BW)
{
    __shared__ float As[32][68];
    __shared__ float Bs[32][128];

    int bid = blockIdx.x;
    int m, local;
    if (bid < 196)      { m = 0; local = bid; }
    else if (bid < 300) { m = 1; local = bid - 196; }
    else if (bid < 364) { m = 2; local = bid - 300; }
    else                { m = 3; local = bid - 364; }

    const float* fm;
    int HW, C, WO, ks; size_t poff;
    if (m == 0)      { fm = f1; HW = 3136; C = 256;  WO = 0;    poff = POFF0; ks = 1; }
    else if (m == 1) { fm = f2; HW = 784;  C = 512;  WO = 256;  poff = POFF1; ks = 2; }
    else if (m == 2) { fm = f3; HW = 196;  C = 1024; WO = 768;  poff = POFF2; ks = 4; }
    else             { fm = f4; HW = 49;   C = 2048; WO = 1792; poff = POFF3; ks = 8; }

    int kt   = local % ks;
    int rest = local / ks;
    int b  = rest & 3;
    int mt = rest >> 2;

    int p0  = mt * 64;
    int kc0 = kt * 256;
    int tid = threadIdx.x;
    int rowg = tid & 7;
    int colg = tid >> 3;
    int r0 = rowg * 8;
    int c0 = colg * 8;

    unsigned long long acc[8][4];
#pragma unroll
    for (int i = 0; i < 8; i++)
#pragma unroll
        for (int j = 0; j < 4; j++) acc[i][j] = 0ULL;

    for (int ch = 0; ch < 8; ch++) {
        int kk = kc0 + ch * 32;
#pragma unroll
        for (int i = 0; i < 16; i++) {
            int lin = tid + i * 128;
            int c = lin >> 6;
            int p = lin & 63;
            float v = 0.f;
            if (p0 + p < HW)
                v = fm[((size_t)b * C + (kk + c)) * HW + p0 + p];
            As[c][p] = v;
        }
#pragma unroll
        for (int i = 0; i < 8; i++) {
            int lin4 = tid + i * 128;
            int k = lin4 >> 5;
            int n4 = (lin4 & 31) * 4;
            float4 v = *(const float4*)&BW[(size_t)(WO + kk + k) * 128 + n4];
            *(float4*)&Bs[k][n4] = v;
        }
        __syncthreads();
#pragma unroll 2
        for (int k = 0; k < 32; k++) {
            float4 aA = *(const float4*)&As[k][r0];
            float4 aB = *(const float4*)&As[k][r0 + 4];
            unsigned long long ad[8] = {dup2(aA.x), dup2(aA.y), dup2(aA.z), dup2(aA.w),
                                        dup2(aB.x), dup2(aB.y), dup2(aB.z), dup2(aB.w)};
            ulonglong2 bp0 = *(const ulonglong2*)&Bs[k][c0];
            ulonglong2 bp1 = *(const ulonglong2*)&Bs[k][c0 + 4];
            unsigned long long bb[4] = {bp0.x, bp0.y, bp1.x, bp1.y};
#pragma unroll
            for (int i = 0; i < 8; i++)
#pragma unroll
                for (int j = 0; j < 4; j++) ffma2(acc[i][j], ad[i], bb[j]);
        }
        __syncthreads();
    }
    size_t pbase = poff + (size_t)b * HW * 128;
#pragma unroll
    for (int i = 0; i < 8; i++) {
        int pix = p0 + r0 + i;
        if (pix >= HW) continue;
        float* dst = &g_P[pbase + (size_t)pix * 128 + c0];
        if (ks == 1) {
#pragma unroll
            for (int j = 0; j < 2; j++) {
                float2 vA = unpk(acc[i][j * 2]);
                float2 vB = unpk(acc[i][j * 2 + 1]);
                *(float4*)&dst[j * 4] = make_float4(vA.x, vA.y, vB.x, vB.y);
            }
        } else {
#pragma unroll
            for (int j = 0; j < 4; j++) {
                float2 v = unpk(acc[i][j]);
                atomicAdd(&dst[j * 2 + 0], v.x);
                atomicAdd(&dst[j * 2 + 1], v.y);
            }
        }
    }
}

// =========================================================================
// Kernel 2: bilinear sampler + bias + relu + assemble X0 row
// =========================================================================
__global__ void sampler_kernel(
    const float* __restrict__ av, const float* __restrict__ vp,
    const float* __restrict__ enc, const float* __restrict__ bias)
{
    int gwarp = (blockIdx.x * blockDim.x + threadIdx.x) >> 5;
    int lane = threadIdx.x & 31;
    if (gwarp >= NV) return;
    int v = gwarp;
    int b = v / VPER;

    float gx = av[(size_t)v * 3 + 0];
    float gy = av[(size_t)v * 3 + 1];

    float4 acc = make_float4(0.f, 0.f, 0.f, 0.f);
#pragma unroll
    for (int m = 0; m < 4; m++) {
        const int DIMm = (m == 0) ? 56 : (m == 1) ? 28 : (m == 2) ? 14 : 7;
        const int HWm  = DIMm * DIMm;
        const size_t POm = (m == 0) ? POFF0 : (m == 1) ? POFF1 : (m == 2) ? POFF2 : POFF3;
        int w = DIMm;
        float fx = (gx + 1.f) * 0.5f * (float)(w - 1);
        float fy = (gy + 1.f) * 0.5f * (float)(w - 1);
        float x0f = floorf(fx), y0f = floorf(fy);
        float wx1 = fx - x0f, wy1 = fy - y0f;
        float wx0 = 1.f - wx1, wy0 = 1.f - wy1;
        int x0 = min(max((int)x0f, 0), w - 1);
        int x1 = min(max((int)x0f + 1, 0), w - 1);
        int y0 = min(max((int)y0f, 0), w - 1);
        int y1 = min(max((int)y0f + 1, 0), w - 1);
        size_t base = POm + (size_t)b * HWm * 128;
        float4 c00 = ((const float4*)&g_P[base + (size_t)(y0 * w + x0) * 128])[lane];
        float4 c01 = ((const float4*)&g_P[base + (size_t)(y0 * w + x1) * 128])[lane];
        float4 c10 = ((const float4*)&g_P[base + (size_t)(y1 * w + x0) * 128])[lane];
        float4 c11 = ((const float4*)&g_P[base + (size_t)(y1 * w + x1) * 128])[lane];
        float w00 = wy0 * wx0, w01 = wy0 * wx1, w10 = wy1 * wx0, w11 = wy1 * wx1;
        acc.x += w00 * c00.x + w01 * c01.x + w10 * c10.x + w11 * c11.x;
        acc.y += w00 * c00.y + w01 * c01.y + w10 * c10.y + w11 * c11.y;
        acc.z += w00 * c00.z + w01 * c01.z + w10 * c10.z + w11 * c11.z;
        acc.w += w00 * c00.w + w01 * c01.w + w10 * c10.w + w11 * c11.w;
    }
    float4 bb = ((const float4*)bias)[lane];
    acc.x = fmaxf(acc.x + bb.x, 0.f);
    acc.y = fmaxf(acc.y + bb.y, 0.f);
    acc.z = fmaxf(acc.z + bb.z, 0.f);
    acc.w = fmaxf(acc.w + bb.w, 0.f);
    float* row = &g_X0[(size_t)v * XSTR];
    ((float4*)row)[lane] = acc;
    if (lane < 3) row[128 + lane] = vp[(size_t)v * 3 + lane];
#pragma unroll
    for (int j = 0; j < 8; j++)
        row[131 + lane * 8 + j] = enc[(size_t)b * 256 + lane * 8 + j];
}

// =========================================================================
// CSR build (edges are INT32)
// =========================================================================
__global__ void hist_kernel(const int* __restrict__ edges, int E)
{
    int i = blockIdx.x * blockDim.x + threadIdx.x;
    if (i >= E) return;
    atomicAdd(&g_cnt[edges[2 * i]], 1);
    atomicAdd(&g_cnt[edges[2 * i + 1]], 1);
}

__global__ void scan_kernel()
{
    __shared__ int part[1024];
    const int n = NV;
    int t = threadIdx.x;
    int chunk = (n + 1023) >> 10;
    int base = t * chunk;
    int sum = 0;
    for (int j = 0; j < chunk; j++) {
        int idx = base + j;
        if (idx < n) sum += g_cnt[idx];
    }
    part[t] = sum;
    __syncthreads();
    for (int off = 1; off < 1024; off <<= 1) {
        int v = 0;
        if (t >= off) v = part[t - off];
        __syncthreads();
        part[t] += v;
        __syncthreads();
    }
    int run = part[t] - sum;
    for (int j = 0; j < chunk; j++) {
        int idx = base + j;
        if (idx < n) { g_offs[idx] = run; run += g_cnt[idx]; }
    }
    if (t == 1023) g_offs[n] = part[1023];
}

__global__ void fill_kernel(const int* __restrict__ edges, int E)
{
    int i = blockIdx.x * blockDim.x + threadIdx.x;
    if (i >= E) return;
    int v0 = edges[2 * i];
    int v1 = edges[2 * i + 1];
    int p0 = atomicAdd(&g_cnt[v0], 1);
    g_entries[g_offs[v0] + p0] = v1;
    int p1 = atomicAdd(&g_cnt[v1], 1);
    g_entries[g_offs[v1] + p1] = v0;
}

// =========================================================================
// fp16x3 dual GEMM via mma.m16n8k16, double-buffered staging (R10 struct).
// =========================================================================
#define BUFW 12288                       // words per buffer
#define SMEM_GEMM_BYTES (2 * BUFW * 4)   // 96 KB

__global__ void __launch_bounds__(512, 1) gemm_f16x3(
    int xsel, int Kin, int reluIn, int img0,
    const float* __restrict__ b0, const float* __restrict__ b1,
    int osel)
{
    extern __shared__ uint32_t smw[];

    const float* X = (xsel == 0) ? g_X0 : (xsel == 1) ? g_bufA : g_bufB;
    int ldx = (xsel == 0) ? XSTR : 128;
    float* H0 = (osel == 1) ? g_bufA : g_bufB;

    int tid = threadIdx.x;
    int lane = tid & 31;
    int wid = tid >> 5;
    int warp_m = wid >> 3;    // 0..1
    int warp_n = wid & 7;     // 0..7
    int row0 = blockIdx.x * 128;

    float d[4][4][4];
#pragma unroll
    for (int mt = 0; mt < 4; mt++)
#pragma unroll
        for (int nt = 0; nt < 4; nt++)
#pragma unroll
            for (int q = 0; q < 4; q++) d[mt][nt][q] = 0.f;

    int nch = (Kin + 31) >> 5;

    auto stage = [&](int c, int buf) {
        uint32_t* sAh = smw + buf * BUFW;
        uint32_t* sAl = sAh + 2048;
        uint32_t* sBh = sAh + 4096;
        uint32_t* sBl = sAh + 8192;
        int kc = c * 32;
        int kmax = min(32, Kin - kc);
        const uint4* src = (const uint4*)&g_pack[(size_t)(img0 + c) * 8192];
#pragma unroll
        for (int i = 0; i < 4; i++) {
            int idx = tid + i * 512;
            uint4 v = src[idx];
            if (idx < 1024) ((uint4*)sBh)[idx] = v;
            else            ((uint4*)sBl)[idx - 1024] = v;
        }
        int r  = tid >> 2;
        int cs = tid & 3;
        int grow = row0 + r;
        float vv[8];
        int cbase = cs * 8;
        if (grow < NV && cbase + 8 <= kmax) {
            float4 p0v = *(const float4*)&X[(size_t)grow * ldx + kc + cbase];
            float4 p1v = *(const float4*)&X[(size_t)grow * ldx + kc + cbase + 4];
            vv[0] = p0v.x; vv[1] = p0v.y; vv[2] = p0v.z; vv[3] = p0v.w;
            vv[4] = p1v.x; vv[5] = p1v.y; vv[6] = p1v.z; vv[7] = p1v.w;
        } else {
#pragma unroll
            for (int j = 0; j < 8; j++) {
                int kk = cbase + j;
                vv[j] = (grow < NV && kk < kmax)
                      ? X[(size_t)grow * ldx + kc + kk] : 0.f;
            }
        }
        __half hh[8], ll[8];
#pragma unroll
        for (int j = 0; j < 8; j++) {
            float x = vv[j];
            if (reluIn) x = fmaxf(x, 0.f);
            __half hi = __float2half_rn(x);
            hh[j] = hi;
            ll[j] = __float2half_rn(x - __half2float(hi));
        }
        int rr = r & 15;
        int blk = (r >> 4) * 2 + (cs >> 1);
        int rg  = (cs & 1) * 2 + ((rr >= 8) ? 1 : 0);
        int wbase = blk * 128 + (rr & 7) * 16 + rg;
#pragma unroll
        for (int t = 0; t < 4; t++) {
            sAh[wbase + t * 4] = pack_h2(hh[2 * t], hh[2 * t + 1]);
            sAl[wbase + t * 4] = pack_h2(ll[2 * t], ll[2 * t + 1]);
        }
    };

    stage(0, 0);
    __syncthreads();

    for (int c = 0; c < nch; c++) {
        int buf = c & 1;
        if (c + 1 < nch) stage(c + 1, buf ^ 1);

        uint32_t* sAh = smw + buf * BUFW;
        uint32_t* sAl = sAh + 2048;
        uint32_t* sBh = sAh + 4096;
        uint32_t* sBl = sAh + 8192;
#pragma unroll
        for (int ks = 0; ks < 2; ks++) {
            uint32_t bh[4][2], bl[4][2];
#pragma unroll
            for (int nt = 0; nt < 4; nt++) {
                int Ni = warp_n * 4 + nt;
                int w = ((Ni * 2 + ks) * 32 + lane) * 2;
                uint2 th = *(const uint2*)&sBh[w];
                uint2 tl = *(const uint2*)&sBl[w];
                bh[nt][0] = th.x; bh[nt][1] = th.y;
                bl[nt][0] = tl.x; bl[nt][1] = tl.y;
            }
#pragma unroll
            for (int mt = 0; mt < 4; mt++) {
                int Mi = warp_m * 4 + mt;
                int w = ((Mi * 2 + ks) * 32 + lane) * 4;
                uint4 th = *(const uint4*)&sAh[w];
                uint4 tl = *(const uint4*)&sAl[w];
                uint32_t ah[4] = {th.x, th.y, th.z, th.w};
                uint32_t al[4] = {tl.x, tl.y, tl.z, tl.w};
#pragma unroll
                for (int nt = 0; nt < 4; nt++) {
                    mma_f16(d[mt][nt], ah, bl[nt]);
                    mma_f16(d[mt][nt], al, bh[nt]);
                    mma_f16(d[mt][nt], ah, bh[nt]);
                }
            }
        }
        __syncthreads();
    }
    // ---- epilogue ----
#pragma unroll
    for (int nt = 0; nt < 4; nt++) {
        int gcol = warp_n * 32 + nt * 8;
        float* Hout; const float* bias; int cb;
        if (gcol < 128) { Hout = H0;   bias = b0; cb = gcol; }
        else            { Hout = g_H1; bias = b1; cb = gcol - 128; }
        int c0 = cb + (lane & 3) * 2;
        float2 bv = *(const float2*)&bias[c0];
#pragma unroll
        for (int mt = 0; mt < 4; mt++) {
            int rtop = row0 + warp_m * 64 + mt * 16 + (lane >> 2);
            if (rtop < NV) {
                float2 o = make_float2(d[mt][nt][0] + bv.x, d[mt][nt][1] + bv.y);
                *(float2*)&Hout[(size_t)rtop * 128 + c0] = o;
            }
            int rbot = rtop + 8;
            if (rbot < NV) {
                float2 o = make_float2(d[mt][nt][2] + bv.x, d[mt][nt][3] + bv.y);
                *(float2*)&Hout[(size_t)rbot * 128 + c0] = o;
            }
        }
    }
}

// =========================================================================
// Gather (MLP-4): OUT[v] += sum_{nb in adj(v)} g_H1[nb]
// =========================================================================
__global__ void gather_kernel(int osel)
{
    float* OUT = (osel == 1) ? g_bufA : g_bufB;
    int gwarp = (blockIdx.x * blockDim.x + threadIdx.x) >> 5;
    int lane = threadIdx.x & 31;
    if (gwarp >= NV) return;
    int v = gwarp;
    int s = g_offs[v], e = g_offs[v + 1];
    float4 acc = ((const float4*)&OUT[(size_t)v * 128])[lane];
    int i = s;
    for (; i + 4 <= e; i += 4) {
        int n0 = g_entries[i + 0];
        int n1 = g_entries[i + 1];
        int n2 = g_entries[i + 2];
        int n3 = g_entries[i + 3];
        float4 h0 = ((const float4*)&g_H1[(size_t)n0 * 128])[lane];
        float4 h1 = ((const float4*)&g_H1[(size_t)n1 * 128])[lane];
        float4 h2 = ((const float4*)&g_H1[(size_t)n2 * 128])[lane];
        float4 h3 = ((const float4*)&g_H1[(size_t)n3 * 128])[lane];
        acc.x += (h0.x + h1.x) + (h2.x + h3.x);
        acc.y += (h0.y + h1.y) + (h2.y + h3.y);
        acc.z += (h0.z + h1.z) + (h2.z + h3.z);
        acc.w += (h0.w + h1.w) + (h2.w + h3.w);
    }
    for (; i < e; i++) {
        int nb = g_entries[i];
        float4 h = ((const float4*)&g_H1[(size_t)nb * 128])[lane];
        acc.x += h.x; acc.y += h.y; acc.z += h.z; acc.w += h.w;
    }
    ((float4*)&OUT[(size_t)v * 128])[lane] = acc;
}

// =========================================================================
// Final projection with FUSED last gather:
//   x = relu(H0[v] + sum_nb g_H1[nb]);  out = x @ off_w + off_b  (128->3)
// =========================================================================
__global__ void final_kernel(int xsel,
                             const float* __restrict__ ow, const float* __restrict__ ob,
                             float* __restrict__ out)
{
    const float* X = (xsel == 1) ? g_bufA : g_bufB;
    int gwarp = (blockIdx.x * blockDim.x + threadIdx.x) >> 5;
    int lane = threadIdx.x & 31;
    if (gwarp >= NV) return;
    int v = gwarp;
    float4 x = ((const float4*)&X[(size_t)v * 128])[lane];
    int s = g_offs[v], e = g_offs[v + 1];
    int i = s;
    for (; i + 4 <= e; i += 4) {
        int n0 = g_entries[i + 0];
        int n1 = g_entries[i + 1];
        int n2 = g_entries[i + 2];
        int n3 = g_entries[i + 3];
        float4 h0 = ((const float4*)&g_H1[(size_t)n0 * 128])[lane];
        float4 h1 = ((const float4*)&g_H1[(size_t)n1 * 128])[lane];
        float4 h2 = ((const float4*)&g_H1[(size_t)n2 * 128])[lane];
        float4 h3 = ((const float4*)&g_H1[(size_t)n3 * 128])[lane];
        x.x += (h0.x + h1.x) + (h2.x + h3.x);
        x.y += (h0.y + h1.y) + (h2.y + h3.y);
        x.z += (h0.z + h1.z) + (h2.z + h3.z);
        x.w += (h0.w + h1.w) + (h2.w + h3.w);
    }
    for (; i < e; i++) {
        int nb = g_entries[i];
        float4 h = ((const float4*)&g_H1[(size_t)nb * 128])[lane];
        x.x += h.x; x.y += h.y; x.z += h.z; x.w += h.w;
    }
    x.x = fmaxf(x.x, 0.f); x.y = fmaxf(x.y, 0.f);
    x.z = fmaxf(x.z, 0.f); x.w = fmaxf(x.w, 0.f);
    const float* wr = &ow[(size_t)(lane * 4) * 3];
    float s0 = x.x * wr[0] + x.y * wr[3] + x.z * wr[6] + x.w * wr[9];
    float s1 = x.x * wr[1] + x.y * wr[4] + x.z * wr[7] + x.w * wr[10];
    float s2 = x.x * wr[2] + x.y * wr[5] + x.z * wr[8] + x.w * wr[11];
#pragma unroll
    for (int o = 16; o > 0; o >>= 1) {
        s0 += __shfl_down_sync(0xffffffffu, s0, o);
        s1 += __shfl_down_sync(0xffffffffu, s1, o);
        s2 += __shfl_down_sync(0xffffffffu, s2, o);
    }
    if (lane == 0) {
        out[(size_t)v * 3 + 0] = s0 + ob[0];
        out[(size_t)v * 3 + 1] = s1 + ob[1];
        out[(size_t)v * 3 + 2] = s2 + ob[2];
    }
}

// =========================================================================
extern "C" void kernel_launch(void* const* d_in, const int* in_sizes, int n_in,
                              void* d_out, int out_size)
{
    const float* f1   = (const float*)d_in[0];
    const float* f2   = (const float*)d_in[1];
    const float* f3   = (const float*)d_in[2];
    const float* f4   = (const float*)d_in[3];
    const float* av   = (const float*)d_in[4];
    const float* vp   = (const float*)d_in[5];
    const float* enc  = (const float*)d_in[6];
    const int*   edges = (const int*)d_in[7];
    const float* bw   = (const float*)d_in[8];
    const float* bb   = (const float*)d_in[9];
    const float* g0w0 = (const float*)d_in[10];
    const float* g0b0 = (const float*)d_in[11];
    const float* g0w1 = (const float*)d_in[12];
    const float* g0b1 = (const float*)d_in[13];
    const float* gw0  = (const float*)d_in[14];
    const float* gb0  = (const float*)d_in[15];
    const float* gw1  = (const float*)d_in[16];
    const float* gb1  = (const float*)d_in[17];
    const float* ow   = (const float*)d_in[18];
    const float* ob   = (const float*)d_in[19];
    float* out = (float*)d_out;

    int E = in_sizes[7] / 2;

    cudaFuncSetAttribute(gemm_f16x3,
                         cudaFuncAttributeMaxDynamicSharedMemorySize,
                         SMEM_GEMM_BYTES);

    const int WARP_GRID = (NV + 7) / 8;
    const int GEMM_GRID = (NV + 127) / 128;   // 321

    // weight prepack (one pass; independent of activations)
    prepack_weights<<<(NIMG * 4096 + 255) / 256, 256>>>(g0w0, g0w1, gw0, gw1);

    // P projection tables (split-K -> zero first)
    zero_P_kernel<<<(PTOT / 4 + 255) / 256, 256>>>();
    precompute_kernel<<<396, 128>>>(f1, f2, f3, f4, bw);
    sampler_kernel<<<WARP_GRID, 256>>>(av, vp, enc, bb);

    // CSR build
    zero_cnt_kernel<<<(NV + 255) / 256, 256>>>();
    hist_kernel<<<(E + 255) / 256, 256>>>(edges, E);
    scan_kernel<<<1, 1024>>>();
    zero_cnt_kernel<<<(NV + 255) / 256, 256>>>();
    fill_kernel<<<(E + 255) / 256, 256>>>(edges, E);

    // layer 0 (Kin=387, no relu on input): images 0..12; H0 -> bufA
    gemm_f16x3<<<GEMM_GRID, 512, SMEM_GEMM_BYTES>>>(0, 387, 0, 0, g0b0, g0b1, 1);
    gather_kernel<<<WARP_GRID, 256>>>(1);

    // layers 1..7 (Kin=128, relu on input), ping-pong bufA <-> bufB.
    // Last layer's gather is fused into final_kernel.
    int cur = 1, nxt = 2;
    for (int i = 0; i < 7; i++) {
        int img0 = 13 + i * 4;
        gemm_f16x3<<<GEMM_GRID, 512, SMEM_GEMM_BYTES>>>(cur, 128, 1, img0,
                                       gb0 + (size_t)i * 128,
                                       gb1 + (size_t)i * 128,
                                       nxt);
        if (i < 6) gather_kernel<<<WARP_GRID, 256>>>(nxt);
        int t = cur; cur = nxt; nxt = t;
    }

    // final: fused last gather + relu + projection
    final_kernel<<<WARP_GRID, 256>>>(cur, ow, ob, out);
}

// round 14
// speedup vs baseline: 1.2955x; 1.1541x over previous
#include <cuda_runtime.h>
#include <cuda_bf16.h>
#include <cuda_fp16.h>
#include <cstdint>

#define NV   40968           // total vertices (B*V)
#define VPER 10242
#define XSTR 392             // padded row stride of X0 (387 used)
#define PTOT 2132480         // total floats in P tables

// P table offsets (floats) per feature map: B*HW*128 cumulative
#define POFF0 0
#define POFF1 1605632
#define POFF2 2007040
#define POFF3 2107392

#define NIMG 41              // weight images (8192 words each)
#define NT128 321            // 128-row A tiles

// ---------------- device scratch (module globals; no allocations) --------
__device__ float g_P[PTOT];
__device__ float g_X0[(size_t)NV * XSTR];
__device__ float g_bufA[(size_t)NV * 128];           // H0 (fp32)
__device__ float g_H1[(size_t)NV * 128];             // H1 (fp32)
__device__ int   g_cnt[NV];
__device__ int   g_offs[NV + 1];
__device__ int   g_entries[245760];
__device__ __align__(16) uint32_t g_pack[NIMG * 8192];
// packed A images: per 128-row tile, 4 chunks x (hi 2048 | lo 2048) words
__device__ __align__(16) uint32_t g_Aimg[(size_t)NT128 * 4 * 4096];

// ---------------- f32x2 helpers (precompute kernel) ----------------
__device__ __forceinline__ unsigned long long dup2(float x) {
    unsigned long long r;
    asm("mov.b64 %0, {%1, %1};" : "=l"(r) : "f"(x));
    return r;
}
__device__ __forceinline__ void ffma2(unsigned long long &d, unsigned long long a, unsigned long long b) {
    asm("fma.rn.f32x2 %0, %1, %2, %0;" : "+l"(d) : "l"(a), "l"(b));
}
__device__ __forceinline__ float2 unpk(unsigned long long v) {
    float2 r;
    asm("mov.b64 {%0, %1}, %2;" : "=f"(r.x), "=f"(r.y) : "l"(v));
    return r;
}

// fp16 mma m16n8k16, f32 accumulate
__device__ __forceinline__ void mma_f16(float* d, const uint32_t* a, const uint32_t* b) {
    asm("mma.sync.aligned.m16n8k16.row.col.f32.f16.f16.f32 "
        "{%0,%1,%2,%3},{%4,%5,%6,%7},{%8,%9},{%0,%1,%2,%3};"
        : "+f"(d[0]), "+f"(d[1]), "+f"(d[2]), "+f"(d[3])
        : "r"(a[0]), "r"(a[1]), "r"(a[2]), "r"(a[3]), "r"(b[0]), "r"(b[1]));
}
__device__ __forceinline__ uint32_t pack_h2(__half a, __half b) {
    __half2 h2 = __halves2half2(a, b);
    return *(uint32_t*)&h2;
}

// =========================================================================
// init kernel: zero P (split-K target) AND prepack weights in one launch.
// zero part: 2083 blocks of 256 (float4 granularity). prepack: 656 blocks.
// =========================================================================
#define ZP_BLOCKS 2083
#define PP_BLOCKS 656
__global__ void init_kernel(
    const float* __restrict__ g0w0, const float* __restrict__ g0w1,
    const float* __restrict__ gw0,  const float* __restrict__ gw1)
{
    if (blockIdx.x < ZP_BLOCKS) {
        int i = blockIdx.x * 256 + threadIdx.x;
        if (i < PTOT / 4) ((float4*)g_P)[i] = make_float4(0.f, 0.f, 0.f, 0.f);
        return;
    }
    int idx = (blockIdx.x - ZP_BLOCKS) * 256 + threadIdx.x;
    if (idx >= NIMG * 4096) return;
    int img = idx >> 12;
    int e   = idx & 4095;
    int n   = e >> 4;          // 0..255
    int kp  = e & 15;          // k-pair 0..15 (k = 2*kp)

    const float *W0, *W1; int Kin, chunk;
    if (img < 13) { W0 = g0w0; W1 = g0w1; Kin = 387; chunk = img; }
    else {
        int t = img - 13;
        int L = t >> 2; chunk = t & 3;
        W0 = gw0 + (size_t)L * 16384;
        W1 = gw1 + (size_t)L * 16384;
        Kin = 128;
    }
    const float* W = (n < 128) ? W0 : W1;
    int col = n & 127;
    int kg = chunk * 32 + kp * 2;
    float w0v = (kg     < Kin) ? W[(size_t)kg * 128 + col]       : 0.f;
    float w1v = (kg + 1 < Kin) ? W[(size_t)(kg + 1) * 128 + col] : 0.f;

    __half h0 = __float2half_rn(w0v);
    __half l0 = __float2half_rn(w0v - __half2float(h0));
    __half h1 = __float2half_rn(w1v);
    __half l1 = __float2half_rn(w1v - __half2float(h1));

    int Ni = n >> 3, nn = n & 7;
    int kk = kp * 2;
    int Ks = kk >> 4;
    int kk16 = kk & 15;
    int rg = (kk16 >= 8) ? 1 : 0;
    int t  = (kk16 & 7) >> 1;
    int word = ((Ni * 2 + Ks) * 32 + nn * 4 + t) * 2 + rg;
    size_t base = (size_t)img * 8192;
    g_pack[base + word]        = pack_h2(h0, h1);
    g_pack[base + 4096 + word] = pack_h2(l0, l1);
}

__global__ void zero_cnt_kernel()
{
    int i = blockIdx.x * blockDim.x + threadIdx.x;
    if (i < NV) g_cnt[i] = 0;
}

// =========================================================================
// Kernel 1: per-pixel projection, split-K balanced, atomicAdd epilogue.
// =========================================================================
__global__ void __launch_bounds__(128) precompute_kernel(
    const float* __restrict__ f1, const float* __restrict__ f2,
    const float* __restrict__ f3, const float* __restrict__ f4,
    const float* __restrict__ BW)
{
    __shared__ float As[32][68];
    __shared__ float Bs[32][128];

    int bid = blockIdx.x;
    int m, local;
    if (bid < 196)      { m = 0; local = bid; }
    else if (bid < 300) { m = 1; local = bid - 196; }
    else if (bid < 364) { m = 2; local = bid - 300; }
    else                { m = 3; local = bid - 364; }

    const float* fm;
    int HW, C, WO, ks; size_t poff;
    if (m == 0)      { fm = f1; HW = 3136; C = 256;  WO = 0;    poff = POFF0; ks = 1; }
    else if (m == 1) { fm = f2; HW = 784;  C = 512;  WO = 256;  poff = POFF1; ks = 2; }
    else if (m == 2) { fm = f3; HW = 196;  C = 1024; WO = 768;  poff = POFF2; ks = 4; }
    else             { fm = f4; HW = 49;   C = 2048; WO = 1792; poff = POFF3; ks = 8; }

    int kt   = local % ks;
    int rest = local / ks;
    int b  = rest & 3;
    int mt = rest >> 2;

    int p0  = mt * 64;
    int kc0 = kt * 256;
    int tid = threadIdx.x;
    int rowg = tid & 7;
    int colg = tid >> 3;
    int r0 = rowg * 8;
    int c0 = colg * 8;

    unsigned long long acc[8][4];
#pragma unroll
    for (int i = 0; i < 8; i++)
#pragma unroll
        for (int j = 0; j < 4; j++) acc[i][j] = 0ULL;

    for (int ch = 0; ch < 8; ch++) {
        int kk = kc0 + ch * 32;
#pragma unroll
        for (int i = 0; i < 16; i++) {
            int lin = tid + i * 128;
            int c = lin >> 6;
            int p = lin & 63;
            float v = 0.f;
            if (p0 + p < HW)
                v = fm[((size_t)b * C + (kk + c)) * HW + p0 + p];
            As[c][p] = v;
        }
#pragma unroll
        for (int i = 0; i < 8; i++) {
            int lin4 = tid + i * 128;
            int k = lin4 >> 5;
            int n4 = (lin4 & 31) * 4;
            float4 v = *(const float4*)&BW[(size_t)(WO + kk + k) * 128 + n4];
            *(float4*)&Bs[k][n4] = v;
        }
        __syncthreads();
#pragma unroll 2
        for (int k = 0; k < 32; k++) {
            float4 aA = *(const float4*)&As[k][r0];
            float4 aB = *(const float4*)&As[k][r0 + 4];
            unsigned long long ad[8] = {dup2(aA.x), dup2(aA.y), dup2(aA.z), dup2(aA.w),
                                        dup2(aB.x), dup2(aB.y), dup2(aB.z), dup2(aB.w)};
            ulonglong2 bp0 = *(const ulonglong2*)&Bs[k][c0];
            ulonglong2 bp1 = *(const ulonglong2*)&Bs[k][c0 + 4];
            unsigned long long bb[4] = {bp0.x, bp0.y, bp1.x, bp1.y};
#pragma unroll
            for (int i = 0; i < 8; i++)
#pragma unroll
                for (int j = 0; j < 4; j++) ffma2(acc[i][j], ad[i], bb[j]);
        }
        __syncthreads();
    }
    size_t pbase = poff + (size_t)b * HW * 128;
#pragma unroll
    for (int i = 0; i < 8; i++) {
        int pix = p0 + r0 + i;
        if (pix >= HW) continue;
        float* dst = &g_P[pbase + (size_t)pix * 128 + c0];
        if (ks == 1) {
#pragma unroll
            for (int j = 0; j < 2; j++) {
                float2 vA = unpk(acc[i][j * 2]);
                float2 vB = unpk(acc[i][j * 2 + 1]);
                *(float4*)&dst[j * 4] = make_float4(vA.x, vA.y, vB.x, vB.y);
            }
        } else {
#pragma unroll
            for (int j = 0; j < 4; j++) {
                float2 v = unpk(acc[i][j]);
                atomicAdd(&dst[j * 2 + 0], v.x);
                atomicAdd(&dst[j * 2 + 1], v.y);
            }
        }
    }
}

// =========================================================================
// Kernel 2: bilinear sampler + bias + relu + assemble X0 row
// =========================================================================
__global__ void sampler_kernel(
    const float* __restrict__ av, const float* __restrict__ vp,
    const float* __restrict__ enc, const float* __restrict__ bias)
{
    int gwarp = (blockIdx.x * blockDim.x + threadIdx.x) >> 5;
    int lane = threadIdx.x & 31;
    if (gwarp >= NV) return;
    int v = gwarp;
    int b = v / VPER;

    float gx = av[(size_t)v * 3 + 0];
    float gy = av[(size_t)v * 3 + 1];

    float4 acc = make_float4(0.f, 0.f, 0.f, 0.f);
#pragma unroll
    for (int m = 0; m < 4; m++) {
        const int DIMm = (m == 0) ? 56 : (m == 1) ? 28 : (m == 2) ? 14 : 7;
        const int HWm  = DIMm * DIMm;
        const size_t POm = (m == 0) ? POFF0 : (m == 1) ? POFF1 : (m == 2) ? POFF2 : POFF3;
        int w = DIMm;
        float fx = (gx + 1.f) * 0.5f * (float)(w - 1);
        float fy = (gy + 1.f) * 0.5f * (float)(w - 1);
        float x0f = floorf(fx), y0f = floorf(fy);
        float wx1 = fx - x0f, wy1 = fy - y0f;
        float wx0 = 1.f - wx1, wy0 = 1.f - wy1;
        int x0 = min(max((int)x0f, 0), w - 1);
        int x1 = min(max((int)x0f + 1, 0), w - 1);
        int y0 = min(max((int)y0f, 0), w - 1);
        int y1 = min(max((int)y0f + 1, 0), w - 1);
        size_t base = POm + (size_t)b * HWm * 128;
        float4 c00 = ((const float4*)&g_P[base + (size_t)(y0 * w + x0) * 128])[lane];
        float4 c01 = ((const float4*)&g_P[base + (size_t)(y0 * w + x1) * 128])[lane];
        float4 c10 = ((const float4*)&g_P[base + (size_t)(y1 * w + x0) * 128])[lane];
        float4 c11 = ((const float4*)&g_P[base + (size_t)(y1 * w + x1) * 128])[lane];
        float w00 = wy0 * wx0, w01 = wy0 * wx1, w10 = wy1 * wx0, w11 = wy1 * wx1;
        acc.x += w00 * c00.x + w01 * c01.x + w10 * c10.x + w11 * c11.x;
        acc.y += w00 * c00.y + w01 * c01.y + w10 * c10.y + w11 * c11.y;
        acc.z += w00 * c00.z + w01 * c01.z + w10 * c10.z + w11 * c11.z;
        acc.w += w00 * c00.w + w01 * c01.w + w10 * c10.w + w11 * c11.w;
    }
    float4 bb = ((const float4*)bias)[lane];
    acc.x = fmaxf(acc.x + bb.x, 0.f);
    acc.y = fmaxf(acc.y + bb.y, 0.f);
    acc.z = fmaxf(acc.z + bb.z, 0.f);
    acc.w = fmaxf(acc.w + bb.w, 0.f);
    float* row = &g_X0[(size_t)v * XSTR];
    ((float4*)row)[lane] = acc;
    if (lane < 3) row[128 + lane] = vp[(size_t)v * 3 + lane];
#pragma unroll
    for (int j = 0; j < 8; j++)
        row[131 + lane * 8 + j] = enc[(size_t)b * 256 + lane * 8 + j];
}

// =========================================================================
// CSR build (edges are INT32)
// =========================================================================
__global__ void hist_kernel(const int* __restrict__ edges, int E)
{
    int i = blockIdx.x * blockDim.x + threadIdx.x;
    if (i >= E) return;
    atomicAdd(&g_cnt[edges[2 * i]], 1);
    atomicAdd(&g_cnt[edges[2 * i + 1]], 1);
}

__global__ void scan_kernel()
{
    __shared__ int part[1024];
    const int n = NV;
    int t = threadIdx.x;
    int chunk = (n + 1023) >> 10;
    int base = t * chunk;
    int sum = 0;
    for (int j = 0; j < chunk; j++) {
        int idx = base + j;
        if (idx < n) sum += g_cnt[idx];
    }
    part[t] = sum;
    __syncthreads();
    for (int off = 1; off < 1024; off <<= 1) {
        int v = 0;
        if (t >= off) v = part[t - off];
        __syncthreads();
        part[t] += v;
        __syncthreads();
    }
    int run = part[t] - sum;
    for (int j = 0; j < chunk; j++) {
        int idx = base + j;
        if (idx < n) { g_offs[idx] = run; run += g_cnt[idx]; }
    }
    if (t == 1023) g_offs[n] = part[1023];
}

// fill via atomicSub (cnt holds degree after hist; no re-zero needed)
__global__ void fill_kernel(const int* __restrict__ edges, int E)
{
    int i = blockIdx.x * blockDim.x + threadIdx.x;
    if (i >= E) return;
    int v0 = edges[2 * i];
    int v1 = edges[2 * i + 1];
    int p0 = atomicSub(&g_cnt[v0], 1) - 1;
    g_entries[g_offs[v0] + p0] = v1;
    int p1 = atomicSub(&g_cnt[v1], 1) - 1;
    g_entries[g_offs[v1] + p1] = v0;
}

// =========================================================================
// Layer-0 GEMM (smem staging from X0, Kin=387) — proven R10 structure.
// =========================================================================
#define BUFW 12288
#define SMEM_GEMM_BYTES (2 * BUFW * 4)

__global__ void __launch_bounds__(512, 1) gemm_l0(
    const float* __restrict__ b0, const float* __restrict__ b1)
{
    extern __shared__ uint32_t smw[];
    const int Kin = 387;
    const float* X = g_X0;
    const int ldx = XSTR;
    float* H0 = g_bufA;

    int tid = threadIdx.x;
    int lane = tid & 31;
    int wid = tid >> 5;
    int warp_m = wid >> 3;
    int warp_n = wid & 7;
    int row0 = blockIdx.x * 128;

    float d[4][4][4];
#pragma unroll
    for (int mt = 0; mt < 4; mt++)
#pragma unroll
        for (int nt = 0; nt < 4; nt++)
#pragma unroll
            for (int q = 0; q < 4; q++) d[mt][nt][q] = 0.f;

    int nch = (Kin + 31) >> 5;   // 13

    auto stage = [&](int c, int buf) {
        uint32_t* sAh = smw + buf * BUFW;
        uint32_t* sAl = sAh + 2048;
        uint32_t* sBh = sAh + 4096;
        uint32_t* sBl = sAh + 8192;
        int kc = c * 32;
        int kmax = min(32, Kin - kc);
        const uint4* src = (const uint4*)&g_pack[(size_t)c * 8192];
#pragma unroll
        for (int i = 0; i < 4; i++) {
            int idx = tid + i * 512;
            uint4 v = src[idx];
            if (idx < 1024) ((uint4*)sBh)[idx] = v;
            else            ((uint4*)sBl)[idx - 1024] = v;
        }
        int r  = tid >> 2;
        int cs = tid & 3;
        int grow = row0 + r;
        float vv[8];
        int cbase = cs * 8;
        if (grow < NV && cbase + 8 <= kmax) {
            float4 p0v = *(const float4*)&X[(size_t)grow * ldx + kc + cbase];
            float4 p1v = *(const float4*)&X[(size_t)grow * ldx + kc + cbase + 4];
            vv[0] = p0v.x; vv[1] = p0v.y; vv[2] = p0v.z; vv[3] = p0v.w;
            vv[4] = p1v.x; vv[5] = p1v.y; vv[6] = p1v.z; vv[7] = p1v.w;
        } else {
#pragma unroll
            for (int j = 0; j < 8; j++) {
                int kk = cbase + j;
                vv[j] = (grow < NV && kk < kmax)
                      ? X[(size_t)grow * ldx + kc + kk] : 0.f;
            }
        }
        __half hh[8], ll[8];
#pragma unroll
        for (int j = 0; j < 8; j++) {
            float x = vv[j];
            __half hi = __float2half_rn(x);
            hh[j] = hi;
            ll[j] = __float2half_rn(x - __half2float(hi));
        }
        int rr = r & 15;
        int blk = (r >> 4) * 2 + (cs >> 1);
        int rg  = (cs & 1) * 2 + ((rr >= 8) ? 1 : 0);
        int wbase = blk * 128 + (rr & 7) * 16 + rg;
#pragma unroll
        for (int t = 0; t < 4; t++) {
            sAh[wbase + t * 4] = pack_h2(hh[2 * t], hh[2 * t + 1]);
            sAl[wbase + t * 4] = pack_h2(ll[2 * t], ll[2 * t + 1]);
        }
    };

    stage(0, 0);
    __syncthreads();

    for (int c = 0; c < nch; c++) {
        int buf = c & 1;
        if (c + 1 < nch) stage(c + 1, buf ^ 1);

        uint32_t* sAh = smw + buf * BUFW;
        uint32_t* sAl = sAh + 2048;
        uint32_t* sBh = sAh + 4096;
        uint32_t* sBl = sAh + 8192;
#pragma unroll
        for (int ks = 0; ks < 2; ks++) {
            uint32_t bh[4][2], bl[4][2];
#pragma unroll
            for (int nt = 0; nt < 4; nt++) {
                int Ni = warp_n * 4 + nt;
                int w = ((Ni * 2 + ks) * 32 + lane) * 2;
                uint2 th = *(const uint2*)&sBh[w];
                uint2 tl = *(const uint2*)&sBl[w];
                bh[nt][0] = th.x; bh[nt][1] = th.y;
                bl[nt][0] = tl.x; bl[nt][1] = tl.y;
            }
#pragma unroll
            for (int mt = 0; mt < 4; mt++) {
                int Mi = warp_m * 4 + mt;
                int w = ((Mi * 2 + ks) * 32 + lane) * 4;
                uint4 th = *(const uint4*)&sAh[w];
                uint4 tl = *(const uint4*)&sAl[w];
                uint32_t ah[4] = {th.x, th.y, th.z, th.w};
                uint32_t al[4] = {tl.x, tl.y, tl.z, tl.w};
#pragma unroll
                for (int nt = 0; nt < 4; nt++) {
                    mma_f16(d[mt][nt], ah, bl[nt]);
                    mma_f16(d[mt][nt], al, bh[nt]);
                    mma_f16(d[mt][nt], ah, bh[nt]);
                }
            }
        }
        __syncthreads();
    }
#pragma unroll
    for (int nt = 0; nt < 4; nt++) {
        int gcol = warp_n * 32 + nt * 8;
        float* Hout; const float* bias; int cb;
        if (gcol < 128) { Hout = H0;   bias = b0; cb = gcol; }
        else            { Hout = g_H1; bias = b1; cb = gcol - 128; }
        int c0 = cb + (lane & 3) * 2;
        float2 bv = *(const float2*)&bias[c0];
#pragma unroll
        for (int mt = 0; mt < 4; mt++) {
            int rtop = row0 + warp_m * 64 + mt * 16 + (lane >> 2);
            if (rtop < NV) {
                float2 o = make_float2(d[mt][nt][0] + bv.x, d[mt][nt][1] + bv.y);
                *(float2*)&Hout[(size_t)rtop * 128 + c0] = o;
            }
            int rbot = rtop + 8;
            if (rbot < NV) {
                float2 o = make_float2(d[mt][nt][2] + bv.x, d[mt][nt][3] + bv.y);
                *(float2*)&Hout[(size_t)rbot * 128 + c0] = o;
            }
        }
    }
}

// =========================================================================
// gather_pack: x = relu(H0[v] + sum_nb H1[nb]) (fp32), split hi/lo fp16,
// write fragment-layout A-image for the next GEMM.
// =========================================================================
__global__ void gather_pack()
{
    int gwarp = (blockIdx.x * blockDim.x + threadIdx.x) >> 5;
    int lane = threadIdx.x & 31;
    if (gwarp >= NV) return;
    int v = gwarp;
    int s = g_offs[v], e = g_offs[v + 1];
    float4 acc = ((const float4*)&g_bufA[(size_t)v * 128])[lane];
    int i = s;
    for (; i + 4 <= e; i += 4) {
        int n0 = g_entries[i + 0];
        int n1 = g_entries[i + 1];
        int n2 = g_entries[i + 2];
        int n3 = g_entries[i + 3];
        float4 h0 = ((const float4*)&g_H1[(size_t)n0 * 128])[lane];
        float4 h1 = ((const float4*)&g_H1[(size_t)n1 * 128])[lane];
        float4 h2 = ((const float4*)&g_H1[(size_t)n2 * 128])[lane];
        float4 h3 = ((const float4*)&g_H1[(size_t)n3 * 128])[lane];
        acc.x += (h0.x + h1.x) + (h2.x + h3.x);
        acc.y += (h0.y + h1.y) + (h2.y + h3.y);
        acc.z += (h0.z + h1.z) + (h2.z + h3.z);
        acc.w += (h0.w + h1.w) + (h2.w + h3.w);
    }
    for (; i < e; i++) {
        int nb = g_entries[i];
        float4 h = ((const float4*)&g_H1[(size_t)nb * 128])[lane];
        acc.x += h.x; acc.y += h.y; acc.z += h.z; acc.w += h.w;
    }
    acc.x = fmaxf(acc.x, 0.f); acc.y = fmaxf(acc.y, 0.f);
    acc.z = fmaxf(acc.z, 0.f); acc.w = fmaxf(acc.w, 0.f);

    // split + pack + fragment-layout store
    __half hx = __float2half_rn(acc.x), hy = __float2half_rn(acc.y);
    __half hz = __float2half_rn(acc.z), hw = __float2half_rn(acc.w);
    __half lx = __float2half_rn(acc.x - __half2float(hx));
    __half ly = __float2half_rn(acc.y - __half2float(hy));
    __half lz = __float2half_rn(acc.z - __half2float(hz));
    __half lw = __float2half_rn(acc.w - __half2float(hw));
    uint32_t hi0 = pack_h2(hx, hy), hi1 = pack_h2(hz, hw);
    uint32_t lo0 = pack_h2(lx, ly), lo1 = pack_h2(lz, lw);

    int tile = v >> 7, r = v & 127;
    int k0 = lane * 4;
    int chunk = k0 >> 5;
    int kin = k0 & 31;
    int cs = kin >> 3;
    int rr = r & 15;
    int blk = (r >> 4) * 2 + (cs >> 1);
    int rg = (cs & 1) * 2 + ((rr >= 8) ? 1 : 0);
    int t = (kin & 7) >> 1;                  // 0 or 2
    int base = blk * 128 + (rr & 7) * 16 + rg;
    uint32_t* cb = &g_Aimg[(size_t)(tile * 4 + chunk) * 4096];
    cb[base + t * 4]        = hi0;
    cb[base + (t + 1) * 4]  = hi1;
    cb[2048 + base + t * 4]       = lo0;
    cb[2048 + base + (t + 1) * 4] = lo1;
}

// =========================================================================
// Smem-less GEMM for layers 1..7 (Kin=128): fragments straight from global.
// 256 threads, tile 64 rows x 256 cols, warp tile 64x32, 2 blocks/SM.
// =========================================================================
__global__ void __launch_bounds__(256, 2) gemm_l128(
    int img0, const float* __restrict__ b0, const float* __restrict__ b1)
{
    int tid = threadIdx.x;
    int lane = tid & 31;
    int warp_n = tid >> 5;       // 0..7
    int gt = blockIdx.x;         // 64-row tile
    int tile128 = gt >> 1, half = gt & 1;
    int row0 = gt * 64;

    float d[4][4][4];
#pragma unroll
    for (int mt = 0; mt < 4; mt++)
#pragma unroll
        for (int nt = 0; nt < 4; nt++)
#pragma unroll
            for (int q = 0; q < 4; q++) d[mt][nt][q] = 0.f;

#pragma unroll
    for (int chunk = 0; chunk < 4; chunk++) {
        const uint32_t* Ab = &g_Aimg[(size_t)(tile128 * 4 + chunk) * 4096];
        const uint32_t* Bb = &g_pack[(size_t)(img0 + chunk) * 8192];
#pragma unroll
        for (int ks = 0; ks < 2; ks++) {
            uint32_t bh[4][2], bl[4][2];
#pragma unroll
            for (int nt = 0; nt < 4; nt++) {
                int Ni = warp_n * 4 + nt;
                int w = ((Ni * 2 + ks) * 32 + lane) * 2;
                uint2 th = *(const uint2*)&Bb[w];
                uint2 tl = *(const uint2*)&Bb[4096 + w];
                bh[nt][0] = th.x; bh[nt][1] = th.y;
                bl[nt][0] = tl.x; bl[nt][1] = tl.y;
            }
#pragma unroll
            for (int mt = 0; mt < 4; mt++) {
                int Mi = half * 4 + mt;
                int w = ((Mi * 2 + ks) * 32 + lane) * 4;
                uint4 th = *(const uint4*)&Ab[w];
                uint4 tl = *(const uint4*)&Ab[2048 + w];
                uint32_t ah[4] = {th.x, th.y, th.z, th.w};
                uint32_t al[4] = {tl.x, tl.y, tl.z, tl.w};
#pragma unroll
                for (int nt = 0; nt < 4; nt++) {
                    mma_f16(d[mt][nt], ah, bl[nt]);
                    mma_f16(d[mt][nt], al, bh[nt]);
                    mma_f16(d[mt][nt], ah, bh[nt]);
                }
            }
        }
    }
    // ---- epilogue ----
#pragma unroll
    for (int nt = 0; nt < 4; nt++) {
        int gcol = warp_n * 32 + nt * 8;
        float* Hout; const float* bias; int cb;
        if (gcol < 128) { Hout = g_bufA; bias = b0; cb = gcol; }
        else            { Hout = g_H1;   bias = b1; cb = gcol - 128; }
        int c0 = cb + (lane & 3) * 2;
        float2 bv = *(const float2*)&bias[c0];
#pragma unroll
        for (int mt = 0; mt < 4; mt++) {
            int rtop = row0 + mt * 16 + (lane >> 2);
            if (rtop < NV) {
                float2 o = make_float2(d[mt][nt][0] + bv.x, d[mt][nt][1] + bv.y);
                *(float2*)&Hout[(size_t)rtop * 128 + c0] = o;
            }
            int rbot = rtop + 8;
            if (rbot < NV) {
                float2 o = make_float2(d[mt][nt][2] + bv.x, d[mt][nt][3] + bv.y);
                *(float2*)&Hout[(size_t)rbot * 128 + c0] = o;
            }
        }
    }
}

// =========================================================================
// Final projection with FUSED last gather:
//   x = relu(H0[v] + sum_nb g_H1[nb]);  out = x @ off_w + off_b  (128->3)
// =========================================================================
__global__ void final_kernel(const float* __restrict__ ow,
                             const float* __restrict__ ob,
                             float* __restrict__ out)
{
    int gwarp = (blockIdx.x * blockDim.x + threadIdx.x) >> 5;
    int lane = threadIdx.x & 31;
    if (gwarp >= NV) return;
    int v = gwarp;
    float4 x = ((const float4*)&g_bufA[(size_t)v * 128])[lane];
    int s = g_offs[v], e = g_offs[v + 1];
    int i = s;
    for (; i + 4 <= e; i += 4) {
        int n0 = g_entries[i + 0];
        int n1 = g_entries[i + 1];
        int n2 = g_entries[i + 2];
        int n3 = g_entries[i + 3];
        float4 h0 = ((const float4*)&g_H1[(size_t)n0 * 128])[lane];
        float4 h1 = ((const float4*)&g_H1[(size_t)n1 * 128])[lane];
        float4 h2 = ((const float4*)&g_H1[(size_t)n2 * 128])[lane];
        float4 h3 = ((const float4*)&g_H1[(size_t)n3 * 128])[lane];
        x.x += (h0.x + h1.x) + (h2.x + h3.x);
        x.y += (h0.y + h1.y) + (h2.y + h3.y);
        x.z += (h0.z + h1.z) + (h2.z + h3.z);
        x.w += (h0.w + h1.w) + (h2.w + h3.w);
    }
    for (; i < e; i++) {
        int nb = g_entries[i];
        float4 h = ((const float4*)&g_H1[(size_t)nb * 128])[lane];
        x.x += h.x; x.y += h.y; x.z += h.z; x.w += h.w;
    }
    x.x = fmaxf(x.x, 0.f); x.y = fmaxf(x.y, 0.f);
    x.z = fmaxf(x.z, 0.f); x.w = fmaxf(x.w, 0.f);
    const float* wr = &ow[(size_t)(lane * 4) * 3];
    float s0 = x.x * wr[0] + x.y * wr[3] + x.z * wr[6] + x.w * wr[9];
    float s1 = x.x * wr[1] + x.y * wr[4] + x.z * wr[7] + x.w * wr[10];
    float s2 = x.x * wr[2] + x.y * wr[5] + x.z * wr[8] + x.w * wr[11];
#pragma unroll
    for (int o = 16; o > 0; o >>= 1) {
        s0 += __shfl_down_sync(0xffffffffu, s0, o);
        s1 += __shfl_down_sync(0xffffffffu, s1, o);
        s2 += __shfl_down_sync(0xffffffffu, s2, o);
    }
    if (lane == 0) {
        out[(size_t)v * 3 + 0] = s0 + ob[0];
        out[(size_t)v * 3 + 1] = s1 + ob[1];
        out[(size_t)v * 3 + 2] = s2 + ob[2];
    }
}

// =========================================================================
extern "C" void kernel_launch(void* const* d_in, const int* in_sizes, int n_in,
                              void* d_out, int out_size)
{
    const float* f1   = (const float*)d_in[0];
    const float* f2   = (const float*)d_in[1];
    const float* f3   = (const float*)d_in[2];
    const float* f4   = (const float*)d_in[3];
    const float* av   = (const float*)d_in[4];
    const float* vp   = (const float*)d_in[5];
    const float* enc  = (const float*)d_in[6];
    const int*   edges = (const int*)d_in[7];
    const float* bw   = (const float*)d_in[8];
    const float* bb   = (const float*)d_in[9];
    const float* g0w0 = (const float*)d_in[10];
    const float* g0b0 = (const float*)d_in[11];
    const float* g0w1 = (const float*)d_in[12];
    const float* g0b1 = (const float*)d_in[13];
    const float* gw0  = (const float*)d_in[14];
    const float* gb0  = (const float*)d_in[15];
    const float* gw1  = (const float*)d_in[16];
    const float* gb1  = (const float*)d_in[17];
    const float* ow   = (const float*)d_in[18];
    const float* ob   = (const float*)d_in[19];
    float* out = (float*)d_out;

    int E = in_sizes[7] / 2;

    cudaFuncSetAttribute(gemm_l0,
                         cudaFuncAttributeMaxDynamicSharedMemorySize,
                         SMEM_GEMM_BYTES);

    const int WARP_GRID = (NV + 7) / 8;

    // (1) zero P + weight prepack fused
    init_kernel<<<ZP_BLOCKS + PP_BLOCKS, 256>>>(g0w0, g0w1, gw0, gw1);
    // (2) P tables, (3) sampler
    precompute_kernel<<<396, 128>>>(f1, f2, f3, f4, bw);
    sampler_kernel<<<WARP_GRID, 256>>>(av, vp, enc, bb);
    // (4) layer-0 GEMM (profiled slot)
    gemm_l0<<<NT128, 512, SMEM_GEMM_BYTES>>>(g0b0, g0b1);

    // CSR build (needed first by gather_pack)
    zero_cnt_kernel<<<(NV + 255) / 256, 256>>>();
    hist_kernel<<<(E + 255) / 256, 256>>>(edges, E);
    scan_kernel<<<1, 1024>>>();
    fill_kernel<<<(E + 255) / 256, 256>>>(edges, E);

    // layers 1..7: gather_pack -> smem-less GEMM
    for (int i = 0; i < 7; i++) {
        gather_pack<<<WARP_GRID, 256>>>();
        gemm_l128<<<(NV + 63) / 64, 256>>>(13 + i * 4,
                                           gb0 + (size_t)i * 128,
                                           gb1 + (size_t)i * 128);
    }

    // final: fused last gather + relu + projection
    final_kernel<<<WARP_GRID, 256>>>(ow, ob, out);
}

// round 15
// speedup vs baseline: 1.4337x; 1.1066x over previous
#include <cuda_runtime.h>
#include <cuda_bf16.h>
#include <cuda_fp16.h>
#include <cstdint>

#define NV   40968           // total vertices (B*V)
#define VPER 10242
#define PTOT 2132480         // total floats in P tables

// P table offsets (floats) per feature map: B*HW*128 cumulative
#define POFF0 0
#define POFF1 1605632
#define POFF2 2007040
#define POFF3 2107392

#define NIMG 41              // weight images (8192 words each)
#define NT128 321            // 128-row A tiles

// ---------------- device scratch (module globals; no allocations) --------
__device__ float g_P[PTOT];
__device__ float g_bufA[(size_t)NV * 128];           // H0 (fp32)
__device__ float g_H1[(size_t)NV * 128];             // H1 (fp32)
__device__ int   g_cnt[NV];
__device__ int   g_offs[NV + 1];
__device__ int   g_entries[245760];
__device__ __align__(16) uint32_t g_pack[NIMG * 8192];
// packed A images, layers 1..7: per 128-row tile, 4 chunks x (hi|lo 2048w)
__device__ __align__(16) uint32_t g_Aimg[(size_t)NT128 * 4 * 4096];
// packed layer-0 input images: per 128-row tile, 13 chunks x (hi|lo 2048w)
__device__ __align__(16) uint32_t g_X0img[(size_t)NT128 * 13 * 4096];

// ---------------- f32x2 helpers (precompute kernel) ----------------
__device__ __forceinline__ unsigned long long dup2(float x) {
    unsigned long long r;
    asm("mov.b64 %0, {%1, %1};" : "=l"(r) : "f"(x));
    return r;
}
__device__ __forceinline__ void ffma2(unsigned long long &d, unsigned long long a, unsigned long long b) {
    asm("fma.rn.f32x2 %0, %1, %2, %0;" : "+l"(d) : "l"(a), "l"(b));
}
__device__ __forceinline__ float2 unpk(unsigned long long v) {
    float2 r;
    asm("mov.b64 {%0, %1}, %2;" : "=f"(r.x), "=f"(r.y) : "l"(v));
    return r;
}

// fp16 mma m16n8k16, f32 accumulate
__device__ __forceinline__ void mma_f16(float* d, const uint32_t* a, const uint32_t* b) {
    asm("mma.sync.aligned.m16n8k16.row.col.f32.f16.f16.f32 "
        "{%0,%1,%2,%3},{%4,%5,%6,%7},{%8,%9},{%0,%1,%2,%3};"
        : "+f"(d[0]), "+f"(d[1]), "+f"(d[2]), "+f"(d[3])
        : "r"(a[0]), "r"(a[1]), "r"(a[2]), "r"(a[3]), "r"(b[0]), "r"(b[1]));
}
__device__ __forceinline__ uint32_t pack_h2(__half a, __half b) {
    __half2 h2 = __halves2half2(a, b);
    return *(uint32_t*)&h2;
}

// store one 4-k group (fp32 values) into a fragment-layout image set
__device__ __forceinline__ void frag_store(
    uint32_t* imgbase, int nchunks_unused, int r, int k0,
    float f0, float f1, float f2, float f3)
{
    __half h0 = __float2half_rn(f0), h1 = __float2half_rn(f1);
    __half h2 = __float2half_rn(f2), h3 = __float2half_rn(f3);
    __half l0 = __float2half_rn(f0 - __half2float(h0));
    __half l1 = __float2half_rn(f1 - __half2float(h1));
    __half l2 = __float2half_rn(f2 - __half2float(h2));
    __half l3 = __float2half_rn(f3 - __half2float(h3));
    int chunk = k0 >> 5;
    int kin = k0 & 31;
    int cs = kin >> 3;
    int rr = r & 15;
    int blk = (r >> 4) * 2 + (cs >> 1);
    int rg = (cs & 1) * 2 + ((rr >= 8) ? 1 : 0);
    int t = (kin & 7) >> 1;
    int base = blk * 128 + (rr & 7) * 16 + rg;
    uint32_t* cb = imgbase + (size_t)chunk * 4096;
    cb[base + t * 4]       = pack_h2(h0, h1);
    cb[base + (t + 1) * 4] = pack_h2(h2, h3);
    cb[2048 + base + t * 4]       = pack_h2(l0, l1);
    cb[2048 + base + (t + 1) * 4] = pack_h2(l2, l3);
}

// =========================================================================
// init kernel: zero P AND prepack weights in one launch.
// =========================================================================
#define ZP_BLOCKS 2083
#define PP_BLOCKS 656
__global__ void init_kernel(
    const float* __restrict__ g0w0, const float* __restrict__ g0w1,
    const float* __restrict__ gw0,  const float* __restrict__ gw1)
{
    if (blockIdx.x < ZP_BLOCKS) {
        int i = blockIdx.x * 256 + threadIdx.x;
        if (i < PTOT / 4) ((float4*)g_P)[i] = make_float4(0.f, 0.f, 0.f, 0.f);
        return;
    }
    int idx = (blockIdx.x - ZP_BLOCKS) * 256 + threadIdx.x;
    if (idx >= NIMG * 4096) return;
    int img = idx >> 12;
    int e   = idx & 4095;
    int n   = e >> 4;          // 0..255
    int kp  = e & 15;          // k-pair 0..15

    const float *W0, *W1; int Kin, chunk;
    if (img < 13) { W0 = g0w0; W1 = g0w1; Kin = 387; chunk = img; }
    else {
        int t = img - 13;
        int L = t >> 2; chunk = t & 3;
        W0 = gw0 + (size_t)L * 16384;
        W1 = gw1 + (size_t)L * 16384;
        Kin = 128;
    }
    const float* W = (n < 128) ? W0 : W1;
    int col = n & 127;
    int kg = chunk * 32 + kp * 2;
    float w0v = (kg     < Kin) ? W[(size_t)kg * 128 + col]       : 0.f;
    float w1v = (kg + 1 < Kin) ? W[(size_t)(kg + 1) * 128 + col] : 0.f;

    __half h0 = __float2half_rn(w0v);
    __half l0 = __float2half_rn(w0v - __half2float(h0));
    __half h1 = __float2half_rn(w1v);
    __half l1 = __float2half_rn(w1v - __half2float(h1));

    int Ni = n >> 3, nn = n & 7;
    int kk = kp * 2;
    int Ks = kk >> 4;
    int kk16 = kk & 15;
    int rg = (kk16 >= 8) ? 1 : 0;
    int t  = (kk16 & 7) >> 1;
    int word = ((Ni * 2 + Ks) * 32 + nn * 4 + t) * 2 + rg;
    size_t base = (size_t)img * 8192;
    g_pack[base + word]        = pack_h2(h0, h1);
    g_pack[base + 4096 + word] = pack_h2(l0, l1);
}

__global__ void zero_cnt_kernel()
{
    int i = blockIdx.x * blockDim.x + threadIdx.x;
    if (i < NV) g_cnt[i] = 0;
}

// =========================================================================
// Kernel 1: per-pixel projection, split-K balanced, atomicAdd epilogue.
// =========================================================================
__global__ void __launch_bounds__(128) precompute_kernel(
    const float* __restrict__ f1, const float* __restrict__ f2,
    const float* __restrict__ f3, const float* __restrict__ f4,
    const float* __restrict__ BW)
{
    __shared__ float As[32][68];
    __shared__ float Bs[32][128];

    int bid = blockIdx.x;
    int m, local;
    if (bid < 196)      { m = 0; local = bid; }
    else if (bid < 300) { m = 1; local = bid - 196; }
    else if (bid < 364) { m = 2; local = bid - 300; }
    else                { m = 3; local = bid - 364; }

    const float* fm;
    int HW, C, WO, ks; size_t poff;
    if (m == 0)      { fm = f1; HW = 3136; C = 256;  WO = 0;    poff = POFF0; ks = 1; }
    else if (m == 1) { fm = f2; HW = 784;  C = 512;  WO = 256;  poff = POFF1; ks = 2; }
    else if (m == 2) { fm = f3; HW = 196;  C = 1024; WO = 768;  poff = POFF2; ks = 4; }
    else             { fm = f4; HW = 49;   C = 2048; WO = 1792; poff = POFF3; ks = 8; }

    int kt   = local % ks;
    int rest = local / ks;
    int b  = rest & 3;
    int mt = rest >> 2;

    int p0  = mt * 64;
    int kc0 = kt * 256;
    int tid = threadIdx.x;
    int rowg = tid & 7;
    int colg = tid >> 3;
    int r0 = rowg * 8;
    int c0 = colg * 8;

    unsigned long long acc[8][4];
#pragma unroll
    for (int i = 0; i < 8; i++)
#pragma unroll
        for (int j = 0; j < 4; j++) acc[i][j] = 0ULL;

    for (int ch = 0; ch < 8; ch++) {
        int kk = kc0 + ch * 32;
#pragma unroll
        for (int i = 0; i < 16; i++) {
            int lin = tid + i * 128;
            int c = lin >> 6;
            int p = lin & 63;
            float v = 0.f;
            if (p0 + p < HW)
                v = fm[((size_t)b * C + (kk + c)) * HW + p0 + p];
            As[c][p] = v;
        }
#pragma unroll
        for (int i = 0; i < 8; i++) {
            int lin4 = tid + i * 128;
            int k = lin4 >> 5;
            int n4 = (lin4 & 31) * 4;
            float4 v = *(const float4*)&BW[(size_t)(WO + kk + k) * 128 + n4];
            *(float4*)&Bs[k][n4] = v;
        }
        __syncthreads();
#pragma unroll 2
        for (int k = 0; k < 32; k++) {
            float4 aA = *(const float4*)&As[k][r0];
            float4 aB = *(const float4*)&As[k][r0 + 4];
            unsigned long long ad[8] = {dup2(aA.x), dup2(aA.y), dup2(aA.z), dup2(aA.w),
                                        dup2(aB.x), dup2(aB.y), dup2(aB.z), dup2(aB.w)};
            ulonglong2 bp0 = *(const ulonglong2*)&Bs[k][c0];
            ulonglong2 bp1 = *(const ulonglong2*)&Bs[k][c0 + 4];
            unsigned long long bb[4] = {bp0.x, bp0.y, bp1.x, bp1.y};
#pragma unroll
            for (int i = 0; i < 8; i++)
#pragma unroll
                for (int j = 0; j < 4; j++) ffma2(acc[i][j], ad[i], bb[j]);
        }
        __syncthreads();
    }
    size_t pbase = poff + (size_t)b * HW * 128;
#pragma unroll
    for (int i = 0; i < 8; i++) {
        int pix = p0 + r0 + i;
        if (pix >= HW) continue;
        float* dst = &g_P[pbase + (size_t)pix * 128 + c0];
        if (ks == 1) {
#pragma unroll
            for (int j = 0; j < 2; j++) {
                float2 vA = unpk(acc[i][j * 2]);
                float2 vB = unpk(acc[i][j * 2 + 1]);
                *(float4*)&dst[j * 4] = make_float4(vA.x, vA.y, vB.x, vB.y);
            }
        } else {
#pragma unroll
            for (int j = 0; j < 4; j++) {
                float2 v = unpk(acc[i][j]);
                atomicAdd(&dst[j * 2 + 0], v.x);
                atomicAdd(&dst[j * 2 + 1], v.y);
            }
        }
    }
}

// =========================================================================
// Kernel 2: bilinear sampler + bias + relu; writes layer-0 fragment images
// DIRECTLY (no X0 buffer). One warp per vertex.
//   k [0,128)   : sampled features (this lane's 4 channels, pass 0)
//   k [128,131) : verts_packed
//   k [131,387) : image_enc
//   k [387,416) : zero pad
// =========================================================================
__global__ void sampler_kernel(
    const float* __restrict__ av, const float* __restrict__ vp,
    const float* __restrict__ enc, const float* __restrict__ bias)
{
    int gwarp = (blockIdx.x * blockDim.x + threadIdx.x) >> 5;
    int lane = threadIdx.x & 31;
    if (gwarp >= NV) return;
    int v = gwarp;
    int b = v / VPER;

    float gx = av[(size_t)v * 3 + 0];
    float gy = av[(size_t)v * 3 + 1];

    float4 acc = make_float4(0.f, 0.f, 0.f, 0.f);
#pragma unroll
    for (int m = 0; m < 4; m++) {
        const int DIMm = (m == 0) ? 56 : (m == 1) ? 28 : (m == 2) ? 14 : 7;
        const int HWm  = DIMm * DIMm;
        const size_t POm = (m == 0) ? POFF0 : (m == 1) ? POFF1 : (m == 2) ? POFF2 : POFF3;
        int w = DIMm;
        float fx = (gx + 1.f) * 0.5f * (float)(w - 1);
        float fy = (gy + 1.f) * 0.5f * (float)(w - 1);
        float x0f = floorf(fx), y0f = floorf(fy);
        float wx1 = fx - x0f, wy1 = fy - y0f;
        float wx0 = 1.f - wx1, wy0 = 1.f - wy1;
        int x0 = min(max((int)x0f, 0), w - 1);
        int x1 = min(max((int)x0f + 1, 0), w - 1);
        int y0 = min(max((int)y0f, 0), w - 1);
        int y1 = min(max((int)y0f + 1, 0), w - 1);
        size_t base = POm + (size_t)b * HWm * 128;
        float4 c00 = ((const float4*)&g_P[base + (size_t)(y0 * w + x0) * 128])[lane];
        float4 c01 = ((const float4*)&g_P[base + (size_t)(y0 * w + x1) * 128])[lane];
        float4 c10 = ((const float4*)&g_P[base + (size_t)(y1 * w + x0) * 128])[lane];
        float4 c11 = ((const float4*)&g_P[base + (size_t)(y1 * w + x1) * 128])[lane];
        float w00 = wy0 * wx0, w01 = wy0 * wx1, w10 = wy1 * wx0, w11 = wy1 * wx1;
        acc.x += w00 * c00.x + w01 * c01.x + w10 * c10.x + w11 * c11.x;
        acc.y += w00 * c00.y + w01 * c01.y + w10 * c10.y + w11 * c11.y;
        acc.z += w00 * c00.z + w01 * c01.z + w10 * c10.z + w11 * c11.z;
        acc.w += w00 * c00.w + w01 * c01.w + w10 * c10.w + w11 * c11.w;
    }
    float4 bb = ((const float4*)bias)[lane];
    acc.x = fmaxf(acc.x + bb.x, 0.f);
    acc.y = fmaxf(acc.y + bb.y, 0.f);
    acc.z = fmaxf(acc.z + bb.z, 0.f);
    acc.w = fmaxf(acc.w + bb.w, 0.f);

    int tile = v >> 7, r = v & 127;
    uint32_t* imgb = &g_X0img[(size_t)tile * 13 * 4096];

    // pass 0: sampled channels
    frag_store(imgb, 13, r, lane * 4, acc.x, acc.y, acc.z, acc.w);
    // passes 1..3: vp / enc / pad
#pragma unroll
    for (int p = 1; p < 4; p++) {
        int k0 = p * 128 + lane * 4;
        if (k0 >= 416) break;
        float f[4];
#pragma unroll
        for (int j = 0; j < 4; j++) {
            int k = k0 + j;
            float val = 0.f;
            if (k < 131)      val = vp[(size_t)v * 3 + (k - 128)];
            else if (k < 387) val = enc[(size_t)b * 256 + (k - 131)];
            f[j] = val;
        }
        frag_store(imgb, 13, r, k0, f[0], f[1], f[2], f[3]);
    }
}

// =========================================================================
// CSR build (edges are INT32)
// =========================================================================
__global__ void hist_kernel(const int* __restrict__ edges, int E)
{
    int i = blockIdx.x * blockDim.x + threadIdx.x;
    if (i >= E) return;
    atomicAdd(&g_cnt[edges[2 * i]], 1);
    atomicAdd(&g_cnt[edges[2 * i + 1]], 1);
}

__global__ void scan_kernel()
{
    __shared__ int part[1024];
    const int n = NV;
    int t = threadIdx.x;
    int chunk = (n + 1023) >> 10;
    int base = t * chunk;
    int sum = 0;
    for (int j = 0; j < chunk; j++) {
        int idx = base + j;
        if (idx < n) sum += g_cnt[idx];
    }
    part[t] = sum;
    __syncthreads();
    for (int off = 1; off < 1024; off <<= 1) {
        int v = 0;
        if (t >= off) v = part[t - off];
        __syncthreads();
        part[t] += v;
        __syncthreads();
    }
    int run = part[t] - sum;
    for (int j = 0; j < chunk; j++) {
        int idx = base + j;
        if (idx < n) { g_offs[idx] = run; run += g_cnt[idx]; }
    }
    if (t == 1023) g_offs[n] = part[1023];
}

__global__ void fill_kernel(const int* __restrict__ edges, int E)
{
    int i = blockIdx.x * blockDim.x + threadIdx.x;
    if (i >= E) return;
    int v0 = edges[2 * i];
    int v1 = edges[2 * i + 1];
    int p0 = atomicSub(&g_cnt[v0], 1) - 1;
    g_entries[g_offs[v0] + p0] = v1;
    int p1 = atomicSub(&g_cnt[v1], 1) - 1;
    g_entries[g_offs[v1] + p1] = v0;
}

// =========================================================================
// Smem-less fragment-streaming dual GEMM (generic chunk count):
//   H0(g_bufA) = x@W0+b0 ; g_H1 = x@W1+b1
// 256 threads, tile 64 rows x 256 cols, warp tile 64x32, 2 blocks/SM.
// A images: aimg + tile128*achunks*4096 ; B images: g_pack + (img0+c)*8192
// =========================================================================
__global__ void __launch_bounds__(256, 2) gemm_frag(
    const uint32_t* __restrict__ aimg, int achunks, int img0,
    const float* __restrict__ b0, const float* __restrict__ b1)
{
    int tid = threadIdx.x;
    int lane = tid & 31;
    int warp_n = tid >> 5;       // 0..7
    int gt = blockIdx.x;         // 64-row tile
    int tile128 = gt >> 1, half = gt & 1;
    int row0 = gt * 64;

    float d[4][4][4];
#pragma unroll
    for (int mt = 0; mt < 4; mt++)
#pragma unroll
        for (int nt = 0; nt < 4; nt++)
#pragma unroll
            for (int q = 0; q < 4; q++) d[mt][nt][q] = 0.f;

#pragma unroll 2
    for (int chunk = 0; chunk < achunks; chunk++) {
        const uint32_t* Ab = aimg + (size_t)(tile128 * achunks + chunk) * 4096;
        const uint32_t* Bb = &g_pack[(size_t)(img0 + chunk) * 8192];
#pragma unroll
        for (int ks = 0; ks < 2; ks++) {
            uint32_t bh[4][2], bl[4][2];
#pragma unroll
            for (int nt = 0; nt < 4; nt++) {
                int Ni = warp_n * 4 + nt;
                int w = ((Ni * 2 + ks) * 32 + lane) * 2;
                uint2 th = *(const uint2*)&Bb[w];
                uint2 tl = *(const uint2*)&Bb[4096 + w];
                bh[nt][0] = th.x; bh[nt][1] = th.y;
                bl[nt][0] = tl.x; bl[nt][1] = tl.y;
            }
#pragma unroll
            for (int mt = 0; mt < 4; mt++) {
                int Mi = half * 4 + mt;
                int w = ((Mi * 2 + ks) * 32 + lane) * 4;
                uint4 th = *(const uint4*)&Ab[w];
                uint4 tl = *(const uint4*)&Ab[2048 + w];
                uint32_t ah[4] = {th.x, th.y, th.z, th.w};
                uint32_t al[4] = {tl.x, tl.y, tl.z, tl.w};
#pragma unroll
                for (int nt = 0; nt < 4; nt++) {
                    mma_f16(d[mt][nt], ah, bl[nt]);
                    mma_f16(d[mt][nt], al, bh[nt]);
                    mma_f16(d[mt][nt], ah, bh[nt]);
                }
            }
        }
    }
    // ---- epilogue ----
#pragma unroll
    for (int nt = 0; nt < 4; nt++) {
        int gcol = warp_n * 32 + nt * 8;
        float* Hout; const float* bias; int cb;
        if (gcol < 128) { Hout = g_bufA; bias = b0; cb = gcol; }
        else            { Hout = g_H1;   bias = b1; cb = gcol - 128; }
        int c0 = cb + (lane & 3) * 2;
        float2 bv = *(const float2*)&bias[c0];
#pragma unroll
        for (int mt = 0; mt < 4; mt++) {
            int rtop = row0 + mt * 16 + (lane >> 2);
            if (rtop < NV) {
                float2 o = make_float2(d[mt][nt][0] + bv.x, d[mt][nt][1] + bv.y);
                *(float2*)&Hout[(size_t)rtop * 128 + c0] = o;
            }
            int rbot = rtop + 8;
            if (rbot < NV) {
                float2 o = make_float2(d[mt][nt][2] + bv.x, d[mt][nt][3] + bv.y);
                *(float2*)&Hout[(size_t)rbot * 128 + c0] = o;
            }
        }
    }
}

// =========================================================================
// gather_pack: x = relu(H0[v] + sum_nb H1[nb]) (fp32), split hi/lo fp16,
// write fragment-layout A-image for the next GEMM.
// =========================================================================
__global__ void gather_pack()
{
    int gwarp = (blockIdx.x * blockDim.x + threadIdx.x) >> 5;
    int lane = threadIdx.x & 31;
    if (gwarp >= NV) return;
    int v = gwarp;
    int s = g_offs[v], e = g_offs[v + 1];
    float4 acc = ((const float4*)&g_bufA[(size_t)v * 128])[lane];
    int i = s;
    for (; i + 4 <= e; i += 4) {
        int n0 = g_entries[i + 0];
        int n1 = g_entries[i + 1];
        int n2 = g_entries[i + 2];
        int n3 = g_entries[i + 3];
        float4 h0 = ((const float4*)&g_H1[(size_t)n0 * 128])[lane];
        float4 h1 = ((const float4*)&g_H1[(size_t)n1 * 128])[lane];
        float4 h2 = ((const float4*)&g_H1[(size_t)n2 * 128])[lane];
        float4 h3 = ((const float4*)&g_H1[(size_t)n3 * 128])[lane];
        acc.x += (h0.x + h1.x) + (h2.x + h3.x);
        acc.y += (h0.y + h1.y) + (h2.y + h3.y);
        acc.z += (h0.z + h1.z) + (h2.z + h3.z);
        acc.w += (h0.w + h1.w) + (h2.w + h3.w);
    }
    for (; i < e; i++) {
        int nb = g_entries[i];
        float4 h = ((const float4*)&g_H1[(size_t)nb * 128])[lane];
        acc.x += h.x; acc.y += h.y; acc.z += h.z; acc.w += h.w;
    }
    acc.x = fmaxf(acc.x, 0.f); acc.y = fmaxf(acc.y, 0.f);
    acc.z = fmaxf(acc.z, 0.f); acc.w = fmaxf(acc.w, 0.f);

    int tile = v >> 7, r = v & 127;
    frag_store(&g_Aimg[(size_t)tile * 4 * 4096], 4, r, lane * 4,
               acc.x, acc.y, acc.z, acc.w);
}

// =========================================================================
// Final projection with FUSED last gather:
//   x = relu(H0[v] + sum_nb g_H1[nb]);  out = x @ off_w + off_b  (128->3)
// =========================================================================
__global__ void final_kernel(const float* __restrict__ ow,
                             const float* __restrict__ ob,
                             float* __restrict__ out)
{
    int gwarp = (blockIdx.x * blockDim.x + threadIdx.x) >> 5;
    int lane = threadIdx.x & 31;
    if (gwarp >= NV) return;
    int v = gwarp;
    float4 x = ((const float4*)&g_bufA[(size_t)v * 128])[lane];
    int s = g_offs[v], e = g_offs[v + 1];
    int i = s;
    for (; i + 4 <= e; i += 4) {
        int n0 = g_entries[i + 0];
        int n1 = g_entries[i + 1];
        int n2 = g_entries[i + 2];
        int n3 = g_entries[i + 3];
        float4 h0 = ((const float4*)&g_H1[(size_t)n0 * 128])[lane];
        float4 h1 = ((const float4*)&g_H1[(size_t)n1 * 128])[lane];
        float4 h2 = ((const float4*)&g_H1[(size_t)n2 * 128])[lane];
        float4 h3 = ((const float4*)&g_H1[(size_t)n3 * 128])[lane];
        x.x += (h0.x + h1.x) + (h2.x + h3.x);
        x.y += (h0.y + h1.y) + (h2.y + h3.y);
        x.z += (h0.z + h1.z) + (h2.z + h3.z);
        x.w += (h0.w + h1.w) + (h2.w + h3.w);
    }
    for (; i < e; i++) {
        int nb = g_entries[i];
        float4 h = ((const float4*)&g_H1[(size_t)nb * 128])[lane];
        x.x += h.x; x.y += h.y; x.z += h.z; x.w += h.w;
    }
    x.x = fmaxf(x.x, 0.f); x.y = fmaxf(x.y, 0.f);
    x.z = fmaxf(x.z, 0.f); x.w = fmaxf(x.w, 0.f);
    const float* wr = &ow[(size_t)(lane * 4) * 3];
    float s0 = x.x * wr[0] + x.y * wr[3] + x.z * wr[6] + x.w * wr[9];
    float s1 = x.x * wr[1] + x.y * wr[4] + x.z * wr[7] + x.w * wr[10];
    float s2 = x.x * wr[2] + x.y * wr[5] + x.z * wr[8] + x.w * wr[11];
#pragma unroll
    for (int o = 16; o > 0; o >>= 1) {
        s0 += __shfl_down_sync(0xffffffffu, s0, o);
        s1 += __shfl_down_sync(0xffffffffu, s1, o);
        s2 += __shfl_down_sync(0xffffffffu, s2, o);
    }
    if (lane == 0) {
        out[(size_t)v * 3 + 0] = s0 + ob[0];
        out[(size_t)v * 3 + 1] = s1 + ob[1];
        out[(size_t)v * 3 + 2] = s2 + ob[2];
    }
}

// =========================================================================
extern "C" void kernel_launch(void* const* d_in, const int* in_sizes, int n_in,
                              void* d_out, int out_size)
{
    const float* f1   = (const float*)d_in[0];
    const float* f2   = (const float*)d_in[1];
    const float* f3   = (const float*)d_in[2];
    const float* f4   = (const float*)d_in[3];
    const float* av   = (const float*)d_in[4];
    const float* vp   = (const float*)d_in[5];
    const float* enc  = (const float*)d_in[6];
    const int*   edges = (const int*)d_in[7];
    const float* bw   = (const float*)d_in[8];
    const float* bb   = (const float*)d_in[9];
    const float* g0w0 = (const float*)d_in[10];
    const float* g0b0 = (const float*)d_in[11];
    const float* g0w1 = (const float*)d_in[12];
    const float* g0b1 = (const float*)d_in[13];
    const float* gw0  = (const float*)d_in[14];
    const float* gb0  = (const float*)d_in[15];
    const float* gw1  = (const float*)d_in[16];
    const float* gb1  = (const float*)d_in[17];
    const float* ow   = (const float*)d_in[18];
    const float* ob   = (const float*)d_in[19];
    float* out = (float*)d_out;

    int E = in_sizes[7] / 2;

    const int WARP_GRID = (NV + 7) / 8;
    const int G64 = (NV + 63) / 64;    // 641

    uint32_t* X0img;
    uint32_t* Aimg;
    cudaGetSymbolAddress((void**)&X0img, g_X0img);
    cudaGetSymbolAddress((void**)&Aimg,  g_Aimg);

    // (1) zero P + weight prepack fused
    init_kernel<<<ZP_BLOCKS + PP_BLOCKS, 256>>>(g0w0, g0w1, gw0, gw1);
    // (2) P tables, (3) sampler -> layer-0 fragment images
    precompute_kernel<<<396, 128>>>(f1, f2, f3, f4, bw);
    sampler_kernel<<<WARP_GRID, 256>>>(av, vp, enc, bb);
    // (4) layer-0 GEMM (smem-less, 13 chunks)
    gemm_frag<<<G64, 256>>>(X0img, 13, 0, g0b0, g0b1);

    // CSR build
    zero_cnt_kernel<<<(NV + 255) / 256, 256>>>();
    hist_kernel<<<(E + 255) / 256, 256>>>(edges, E);
    scan_kernel<<<1, 1024>>>();
    fill_kernel<<<(E + 255) / 256, 256>>>(edges, E);

    // layers 1..7: gather_pack -> smem-less GEMM (4 chunks)
    for (int i = 0; i < 7; i++) {
        gather_pack<<<WARP_GRID, 256>>>();
        gemm_frag<<<G64, 256>>>(Aimg, 4, 13 + i * 4,
                                gb0 + (size_t)i * 128,
                                gb1 + (size_t)i * 128);
    }

    // final: fused last gather + relu + projection
    final_kernel<<<WARP_GRID, 256>>>(ow, ob, out);
}

// round 16
// speedup vs baseline: 1.4645x; 1.0215x over previous
#include <cuda_runtime.h>
#include <cuda_bf16.h>
#include <cuda_fp16.h>
#include <cstdint>

#define NV   40968           // total vertices (B*V)
#define VPER 10242
#define PTOT 2132480         // total floats in P tables

// P table offsets (floats) per feature map: B*HW*128 cumulative
#define POFF0 0
#define POFF1 1605632
#define POFF2 2007040
#define POFF3 2107392

#define NIMG 41              // weight images (8192 words each)
#define NT128 321            // 128-row A tiles

// ---------------- device scratch (module globals; no allocations) --------
__device__ float g_P[PTOT];
__device__ float g_bufA[(size_t)NV * 128];           // H0 (fp32)
__device__ float g_H1[(size_t)NV * 128];             // H1 (fp32)
__device__ int   g_cnt[NV];
__device__ int   g_offs[NV + 1];
__device__ int   g_entries[245760];
__device__ __align__(16) uint32_t g_pack[NIMG * 8192];
// packed A images, layers 1..7: per 128-row tile, 4 chunks x (hi|lo 2048w)
__device__ __align__(16) uint32_t g_Aimg[(size_t)NT128 * 4 * 4096];
// packed layer-0 input images: per 128-row tile, 13 chunks x (hi|lo 2048w)
__device__ __align__(16) uint32_t g_X0img[(size_t)NT128 * 13 * 4096];

// ---------------- f32x2 helpers (precompute kernel) ----------------
__device__ __forceinline__ unsigned long long dup2(float x) {
    unsigned long long r;
    asm("mov.b64 %0, {%1, %1};" : "=l"(r) : "f"(x));
    return r;
}
__device__ __forceinline__ void ffma2(unsigned long long &d, unsigned long long a, unsigned long long b) {
    asm("fma.rn.f32x2 %0, %1, %2, %0;" : "+l"(d) : "l"(a), "l"(b));
}
__device__ __forceinline__ float2 unpk(unsigned long long v) {
    float2 r;
    asm("mov.b64 {%0, %1}, %2;" : "=f"(r.x), "=f"(r.y) : "l"(v));
    return r;
}

// fp16 mma m16n8k16, f32 accumulate
__device__ __forceinline__ void mma_f16(float* d, const uint32_t* a, const uint32_t* b) {
    asm("mma.sync.aligned.m16n8k16.row.col.f32.f16.f16.f32 "
        "{%0,%1,%2,%3},{%4,%5,%6,%7},{%8,%9},{%0,%1,%2,%3};"
        : "+f"(d[0]), "+f"(d[1]), "+f"(d[2]), "+f"(d[3])
        : "r"(a[0]), "r"(a[1]), "r"(a[2]), "r"(a[3]), "r"(b[0]), "r"(b[1]));
}
__device__ __forceinline__ uint32_t pack_h2(__half a, __half b) {
    __half2 h2 = __halves2half2(a, b);
    return *(uint32_t*)&h2;
}

// cp.async helpers
__device__ __forceinline__ void cpa16(uint32_t saddr, const void* gaddr) {
    asm volatile("cp.async.cg.shared.global [%0], [%1], 16;"
                 :: "r"(saddr), "l"(gaddr));
}
__device__ __forceinline__ void cpa_commit() {
    asm volatile("cp.async.commit_group;" ::: "memory");
}
template <int N>
__device__ __forceinline__ void cpa_wait() {
    asm volatile("cp.async.wait_group %0;" :: "n"(N) : "memory");
}

// store one 4-k group (fp32 values) into a fragment-layout image set
__device__ __forceinline__ void frag_store(
    uint32_t* imgbase, int nchunks_unused, int r, int k0,
    float f0, float f1, float f2, float f3)
{
    __half h0 = __float2half_rn(f0), h1 = __float2half_rn(f1);
    __half h2 = __float2half_rn(f2), h3 = __float2half_rn(f3);
    __half l0 = __float2half_rn(f0 - __half2float(h0));
    __half l1 = __float2half_rn(f1 - __half2float(h1));
    __half l2 = __float2half_rn(f2 - __half2float(h2));
    __half l3 = __float2half_rn(f3 - __half2float(h3));
    int chunk = k0 >> 5;
    int kin = k0 & 31;
    int cs = kin >> 3;
    int rr = r & 15;
    int blk = (r >> 4) * 2 + (cs >> 1);
    int rg = (cs & 1) * 2 + ((rr >= 8) ? 1 : 0);
    int t = (kin & 7) >> 1;
    int base = blk * 128 + (rr & 7) * 16 + rg;
    uint32_t* cb = imgbase + (size_t)chunk * 4096;
    cb[base + t * 4]       = pack_h2(h0, h1);
    cb[base + (t + 1) * 4] = pack_h2(h2, h3);
    cb[2048 + base + t * 4]       = pack_h2(l0, l1);
    cb[2048 + base + (t + 1) * 4] = pack_h2(l2, l3);
}

// =========================================================================
// init kernel: zero P AND prepack weights in one launch.
// =========================================================================
#define ZP_BLOCKS 2083
#define PP_BLOCKS 656
__global__ void init_kernel(
    const float* __restrict__ g0w0, const float* __restrict__ g0w1,
    const float* __restrict__ gw0,  const float* __restrict__ gw1)
{
    if (blockIdx.x < ZP_BLOCKS) {
        int i = blockIdx.x * 256 + threadIdx.x;
        if (i < PTOT / 4) ((float4*)g_P)[i] = make_float4(0.f, 0.f, 0.f, 0.f);
        return;
    }
    int idx = (blockIdx.x - ZP_BLOCKS) * 256 + threadIdx.x;
    if (idx >= NIMG * 4096) return;
    int img = idx >> 12;
    int e   = idx & 4095;
    int n   = e >> 4;
    int kp  = e & 15;

    const float *W0, *W1; int Kin, chunk;
    if (img < 13) { W0 = g0w0; W1 = g0w1; Kin = 387; chunk = img; }
    else {
        int t = img - 13;
        int L = t >> 2; chunk = t & 3;
        W0 = gw0 + (size_t)L * 16384;
        W1 = gw1 + (size_t)L * 16384;
        Kin = 128;
    }
    const float* W = (n < 128) ? W0 : W1;
    int col = n & 127;
    int kg = chunk * 32 + kp * 2;
    float w0v = (kg     < Kin) ? W[(size_t)kg * 128 + col]       : 0.f;
    float w1v = (kg + 1 < Kin) ? W[(size_t)(kg + 1) * 128 + col] : 0.f;

    __half h0 = __float2half_rn(w0v);
    __half l0 = __float2half_rn(w0v - __half2float(h0));
    __half h1 = __float2half_rn(w1v);
    __half l1 = __float2half_rn(w1v - __half2float(h1));

    int Ni = n >> 3, nn = n & 7;
    int kk = kp * 2;
    int Ks = kk >> 4;
    int kk16 = kk & 15;
    int rg = (kk16 >= 8) ? 1 : 0;
    int t  = (kk16 & 7) >> 1;
    int word = ((Ni * 2 + Ks) * 32 + nn * 4 + t) * 2 + rg;
    size_t base = (size_t)img * 8192;
    g_pack[base + word]        = pack_h2(h0, h1);
    g_pack[base + 4096 + word] = pack_h2(l0, l1);
}

__global__ void zero_cnt_kernel()
{
    int i = blockIdx.x * blockDim.x + threadIdx.x;
    if (i < NV) g_cnt[i] = 0;
}

// =========================================================================
// Kernel 1: per-pixel projection, split-K balanced, atomicAdd epilogue.
// =========================================================================
__global__ void __launch_bounds__(128) precompute_kernel(
    const float* __restrict__ f1, const float* __restrict__ f2,
    const float* __restrict__ f3, const float* __restrict__ f4,
    const float* __restrict__ BW)
{
    __shared__ float As[32][68];
    __shared__ float Bs[32][128];

    int bid = blockIdx.x;
    int m, local;
    if (bid < 196)      { m = 0; local = bid; }
    else if (bid < 300) { m = 1; local = bid - 196; }
    else if (bid < 364) { m = 2; local = bid - 300; }
    else                { m = 3; local = bid - 364; }

    const float* fm;
    int HW, C, WO, ks; size_t poff;
    if (m == 0)      { fm = f1; HW = 3136; C = 256;  WO = 0;    poff = POFF0; ks = 1; }
    else if (m == 1) { fm = f2; HW = 784;  C = 512;  WO = 256;  poff = POFF1; ks = 2; }
    else if (m == 2) { fm = f3; HW = 196;  C = 1024; WO = 768;  poff = POFF2; ks = 4; }
    else             { fm = f4; HW = 49;   C = 2048; WO = 1792; poff = POFF3; ks = 8; }

    int kt   = local % ks;
    int rest = local / ks;
    int b  = rest & 3;
    int mt = rest >> 2;

    int p0  = mt * 64;
    int kc0 = kt * 256;
    int tid = threadIdx.x;
    int rowg = tid & 7;
    int colg = tid >> 3;
    int r0 = rowg * 8;
    int c0 = colg * 8;

    unsigned long long acc[8][4];
#pragma unroll
    for (int i = 0; i < 8; i++)
#pragma unroll
        for (int j = 0; j < 4; j++) acc[i][j] = 0ULL;

    for (int ch = 0; ch < 8; ch++) {
        int kk = kc0 + ch * 32;
#pragma unroll
        for (int i = 0; i < 16; i++) {
            int lin = tid + i * 128;
            int c = lin >> 6;
            int p = lin & 63;
            float v = 0.f;
            if (p0 + p < HW)
                v = fm[((size_t)b * C + (kk + c)) * HW + p0 + p];
            As[c][p] = v;
        }
#pragma unroll
        for (int i = 0; i < 8; i++) {
            int lin4 = tid + i * 128;
            int k = lin4 >> 5;
            int n4 = (lin4 & 31) * 4;
            float4 v = *(const float4*)&BW[(size_t)(WO + kk + k) * 128 + n4];
            *(float4*)&Bs[k][n4] = v;
        }
        __syncthreads();
#pragma unroll 2
        for (int k = 0; k < 32; k++) {
            float4 aA = *(const float4*)&As[k][r0];
            float4 aB = *(const float4*)&As[k][r0 + 4];
            unsigned long long ad[8] = {dup2(aA.x), dup2(aA.y), dup2(aA.z), dup2(aA.w),
                                        dup2(aB.x), dup2(aB.y), dup2(aB.z), dup2(aB.w)};
            ulonglong2 bp0 = *(const ulonglong2*)&Bs[k][c0];
            ulonglong2 bp1 = *(const ulonglong2*)&Bs[k][c0 + 4];
            unsigned long long bb[4] = {bp0.x, bp0.y, bp1.x, bp1.y};
#pragma unroll
            for (int i = 0; i < 8; i++)
#pragma unroll
                for (int j = 0; j < 4; j++) ffma2(acc[i][j], ad[i], bb[j]);
        }
        __syncthreads();
    }
    size_t pbase = poff + (size_t)b * HW * 128;
#pragma unroll
    for (int i = 0; i < 8; i++) {
        int pix = p0 + r0 + i;
        if (pix >= HW) continue;
        float* dst = &g_P[pbase + (size_t)pix * 128 + c0];
        if (ks == 1) {
#pragma unroll
            for (int j = 0; j < 2; j++) {
                float2 vA = unpk(acc[i][j * 2]);
                float2 vB = unpk(acc[i][j * 2 + 1]);
                *(float4*)&dst[j * 4] = make_float4(vA.x, vA.y, vB.x, vB.y);
            }
        } else {
#pragma unroll
            for (int j = 0; j < 4; j++) {
                float2 v = unpk(acc[i][j]);
                atomicAdd(&dst[j * 2 + 0], v.x);
                atomicAdd(&dst[j * 2 + 1], v.y);
            }
        }
    }
}

// =========================================================================
// Kernel 2: bilinear sampler + bias + relu; writes layer-0 fragment images
// =========================================================================
__global__ void sampler_kernel(
    const float* __restrict__ av, const float* __restrict__ vp,
    const float* __restrict__ enc, const float* __restrict__ bias)
{
    int gwarp = (blockIdx.x * blockDim.x + threadIdx.x) >> 5;
    int lane = threadIdx.x & 31;
    if (gwarp >= NV) return;
    int v = gwarp;
    int b = v / VPER;

    float gx = av[(size_t)v * 3 + 0];
    float gy = av[(size_t)v * 3 + 1];

    float4 acc = make_float4(0.f, 0.f, 0.f, 0.f);
#pragma unroll
    for (int m = 0; m < 4; m++) {
        const int DIMm = (m == 0) ? 56 : (m == 1) ? 28 : (m == 2) ? 14 : 7;
        const int HWm  = DIMm * DIMm;
        const size_t POm = (m == 0) ? POFF0 : (m == 1) ? POFF1 : (m == 2) ? POFF2 : POFF3;
        int w = DIMm;
        float fx = (gx + 1.f) * 0.5f * (float)(w - 1);
        float fy = (gy + 1.f) * 0.5f * (float)(w - 1);
        float x0f = floorf(fx), y0f = floorf(fy);
        float wx1 = fx - x0f, wy1 = fy - y0f;
        float wx0 = 1.f - wx1, wy0 = 1.f - wy1;
        int x0 = min(max((int)x0f, 0), w - 1);
        int x1 = min(max((int)x0f + 1, 0), w - 1);
        int y0 = min(max((int)y0f, 0), w - 1);
        int y1 = min(max((int)y0f + 1, 0), w - 1);
        size_t base = POm + (size_t)b * HWm * 128;
        float4 c00 = ((const float4*)&g_P[base + (size_t)(y0 * w + x0) * 128])[lane];
        float4 c01 = ((const float4*)&g_P[base + (size_t)(y0 * w + x1) * 128])[lane];
        float4 c10 = ((const float4*)&g_P[base + (size_t)(y1 * w + x0) * 128])[lane];
        float4 c11 = ((const float4*)&g_P[base + (size_t)(y1 * w + x1) * 128])[lane];
        float w00 = wy0 * wx0, w01 = wy0 * wx1, w10 = wy1 * wx0, w11 = wy1 * wx1;
        acc.x += w00 * c00.x + w01 * c01.x + w10 * c10.x + w11 * c11.x;
        acc.y += w00 * c00.y + w01 * c01.y + w10 * c10.y + w11 * c11.y;
        acc.z += w00 * c00.z + w01 * c01.z + w10 * c10.z + w11 * c11.z;
        acc.w += w00 * c00.w + w01 * c01.w + w10 * c10.w + w11 * c11.w;
    }
    float4 bb = ((const float4*)bias)[lane];
    acc.x = fmaxf(acc.x + bb.x, 0.f);
    acc.y = fmaxf(acc.y + bb.y, 0.f);
    acc.z = fmaxf(acc.z + bb.z, 0.f);
    acc.w = fmaxf(acc.w + bb.w, 0.f);

    int tile = v >> 7, r = v & 127;
    uint32_t* imgb = &g_X0img[(size_t)tile * 13 * 4096];

    frag_store(imgb, 13, r, lane * 4, acc.x, acc.y, acc.z, acc.w);
#pragma unroll
    for (int p = 1; p < 4; p++) {
        int k0 = p * 128 + lane * 4;
        if (k0 >= 416) break;
        float f[4];
#pragma unroll
        for (int j = 0; j < 4; j++) {
            int k = k0 + j;
            float val = 0.f;
            if (k < 131)      val = vp[(size_t)v * 3 + (k - 128)];
            else if (k < 387) val = enc[(size_t)b * 256 + (k - 131)];
            f[j] = val;
        }
        frag_store(imgb, 13, r, k0, f[0], f[1], f[2], f[3]);
    }
}

// =========================================================================
// CSR build (edges are INT32)
// =========================================================================
__global__ void hist_kernel(const int* __restrict__ edges, int E)
{
    int i = blockIdx.x * blockDim.x + threadIdx.x;
    if (i >= E) return;
    atomicAdd(&g_cnt[edges[2 * i]], 1);
    atomicAdd(&g_cnt[edges[2 * i + 1]], 1);
}

__global__ void scan_kernel()
{
    __shared__ int part[1024];
    const int n = NV;
    int t = threadIdx.x;
    int chunk = (n + 1023) >> 10;
    int base = t * chunk;
    int sum = 0;
    for (int j = 0; j < chunk; j++) {
        int idx = base + j;
        if (idx < n) sum += g_cnt[idx];
    }
    part[t] = sum;
    __syncthreads();
    for (int off = 1; off < 1024; off <<= 1) {
        int v = 0;
        if (t >= off) v = part[t - off];
        __syncthreads();
        part[t] += v;
        __syncthreads();
    }
    int run = part[t] - sum;
    for (int j = 0; j < chunk; j++) {
        int idx = base + j;
        if (idx < n) { g_offs[idx] = run; run += g_cnt[idx]; }
    }
    if (t == 1023) g_offs[n] = part[1023];
}

__global__ void fill_kernel(const int* __restrict__ edges, int E)
{
    int i = blockIdx.x * blockDim.x + threadIdx.x;
    if (i >= E) return;
    int v0 = edges[2 * i];
    int v1 = edges[2 * i + 1];
    int p0 = atomicSub(&g_cnt[v0], 1) - 1;
    g_entries[g_offs[v0] + p0] = v1;
    int p1 = atomicSub(&g_cnt[v1], 1) - 1;
    g_entries[g_offs[v1] + p1] = v0;
}

// =========================================================================
// cp.async-pipelined fragment GEMM:
//   H0(g_bufA) = x@W0+b0 ; g_H1 = x@W1+b1
// 256 threads, tile 64 rows x 256 cols, warp tile 64x32, 2 blocks/SM.
// Double-buffered smem stages: [Ah 1024 | Al 1024 | Bh 4096 | Bl 4096] words.
// =========================================================================
#define STW 10240                       // words per stage
#define SMEM_GEMM_BYTES (2 * STW * 4)   // 80 KB

__global__ void __launch_bounds__(256, 2) gemm_frag(
    const uint32_t* __restrict__ aimg, int achunks, int img0,
    const float* __restrict__ b0, const float* __restrict__ b1)
{
    extern __shared__ uint32_t smw[];
    uint32_t smem_base = (uint32_t)__cvta_generic_to_shared(smw);

    int tid = threadIdx.x;
    int lane = tid & 31;
    int warp_n = tid >> 5;       // 0..7
    int gt = blockIdx.x;         // 64-row tile
    int tile128 = gt >> 1, half = gt & 1;
    int row0 = gt * 64;

    float d[4][4][4];
#pragma unroll
    for (int mt = 0; mt < 4; mt++)
#pragma unroll
        for (int nt = 0; nt < 4; nt++)
#pragma unroll
            for (int q = 0; q < 4; q++) d[mt][nt][q] = 0.f;

    // issue cp.async copies for chunk c into stage s
    auto issue = [&](int c, int s) {
        const uint32_t* Asrc = aimg + (size_t)(tile128 * achunks + c) * 4096
                               + half * 1024;
        const uint32_t* Bsrc = &g_pack[(size_t)(img0 + c) * 8192];
        uint32_t sb = smem_base + s * (STW * 4);
        // A hi: 256 uint4, A lo: 256 uint4  (1 each per thread)
        cpa16(sb + tid * 16,                 Asrc + tid * 4);
        cpa16(sb + 4096 + tid * 16,          Asrc + 2048 + tid * 4);
        // B hi: 1024 uint4, B lo: 1024 uint4 (4 each per thread)
#pragma unroll
        for (int i = 0; i < 4; i++) {
            int u = tid + i * 256;
            cpa16(sb + 8192  + u * 16, Bsrc + u * 4);
            cpa16(sb + 24576 + u * 16, Bsrc + 4096 + u * 4);
        }
        cpa_commit();
    };

    issue(0, 0);
    if (achunks > 1) issue(1, 1);

    for (int c = 0; c < achunks; c++) {
        if (c + 2 <= achunks - 1) cpa_wait<1>();  // more groups in flight
        else                      cpa_wait<0>();  // last pending group
        __syncthreads();

        int s = c & 1;
        const uint32_t* Ah = smw + s * STW;
        const uint32_t* Al = Ah + 1024;
        const uint32_t* Bh = Ah + 2048;
        const uint32_t* Bl = Ah + 6144;
#pragma unroll
        for (int ks = 0; ks < 2; ks++) {
            uint32_t bh[4][2], bl[4][2];
#pragma unroll
            for (int nt = 0; nt < 4; nt++) {
                int Ni = warp_n * 4 + nt;
                int w = ((Ni * 2 + ks) * 32 + lane) * 2;
                uint2 th = *(const uint2*)&Bh[w];
                uint2 tl = *(const uint2*)&Bl[w];
                bh[nt][0] = th.x; bh[nt][1] = th.y;
                bl[nt][0] = tl.x; bl[nt][1] = tl.y;
            }
#pragma unroll
            for (int mt = 0; mt < 4; mt++) {
                int w = ((mt * 2 + ks) * 32 + lane) * 4;   // wrong for mt>1? no: local blk = mt*2+ks? see note
                // local A layout: blk_local = (local r>>4)*2 + (cs>>1) with
                // local rows 0..63 -> blk_local 0..7 == (Mi-half*4)*2+ks
                uint4 th = *(const uint4*)&Ah[w];
                uint4 tl = *(const uint4*)&Al[w];
                uint32_t ah[4] = {th.x, th.y, th.z, th.w};
                uint32_t al[4] = {tl.x, tl.y, tl.z, tl.w};
#pragma unroll
                for (int nt = 0; nt < 4; nt++) {
                    mma_f16(d[mt][nt], ah, bl[nt]);
                    mma_f16(d[mt][nt], al, bh[nt]);
                    mma_f16(d[mt][nt], ah, bh[nt]);
                }
            }
        }
        __syncthreads();
        if (c + 2 < achunks) issue(c + 2, s);
    }
    // ---- epilogue ----
#pragma unroll
    for (int nt = 0; nt < 4; nt++) {
        int gcol = warp_n * 32 + nt * 8;
        float* Hout; const float* bias; int cb;
        if (gcol < 128) { Hout = g_bufA; bias = b0; cb = gcol; }
        else            { Hout = g_H1;   bias = b1; cb = gcol - 128; }
        int c0 = cb + (lane & 3) * 2;
        float2 bv = *(const float2*)&bias[c0];
#pragma unroll
        for (int mt = 0; mt < 4; mt++) {
            int rtop = row0 + mt * 16 + (lane >> 2);
            if (rtop < NV) {
                float2 o = make_float2(d[mt][nt][0] + bv.x, d[mt][nt][1] + bv.y);
                *(float2*)&Hout[(size_t)rtop * 128 + c0] = o;
            }
            int rbot = rtop + 8;
            if (rbot < NV) {
                float2 o = make_float2(d[mt][nt][2] + bv.x, d[mt][nt][3] + bv.y);
                *(float2*)&Hout[(size_t)rbot * 128 + c0] = o;
            }
        }
    }
}

// =========================================================================
// gather_pack: x = relu(H0[v] + sum_nb H1[nb]) (fp32), split hi/lo fp16,
// write fragment-layout A-image for the next GEMM.
// =========================================================================
__global__ void gather_pack()
{
    int gwarp = (blockIdx.x * blockDim.x + threadIdx.x) >> 5;
    int lane = threadIdx.x & 31;
    if (gwarp >= NV) return;
    int v = gwarp;
    int s = g_offs[v], e = g_offs[v + 1];
    float4 acc = ((const float4*)&g_bufA[(size_t)v * 128])[lane];
    int i = s;
    for (; i + 4 <= e; i += 4) {
        int n0 = g_entries[i + 0];
        int n1 = g_entries[i + 1];
        int n2 = g_entries[i + 2];
        int n3 = g_entries[i + 3];
        float4 h0 = ((const float4*)&g_H1[(size_t)n0 * 128])[lane];
        float4 h1 = ((const float4*)&g_H1[(size_t)n1 * 128])[lane];
        float4 h2 = ((const float4*)&g_H1[(size_t)n2 * 128])[lane];
        float4 h3 = ((const float4*)&g_H1[(size_t)n3 * 128])[lane];
        acc.x += (h0.x + h1.x) + (h2.x + h3.x);
        acc.y += (h0.y + h1.y) + (h2.y + h3.y);
        acc.z += (h0.z + h1.z) + (h2.z + h3.z);
        acc.w += (h0.w + h1.w) + (h2.w + h3.w);
    }
    for (; i < e; i++) {
        int nb = g_entries[i];
        float4 h = ((const float4*)&g_H1[(size_t)nb * 128])[lane];
        acc.x += h.x; acc.y += h.y; acc.z += h.z; acc.w += h.w;
    }
    acc.x = fmaxf(acc.x, 0.f); acc.y = fmaxf(acc.y, 0.f);
    acc.z = fmaxf(acc.z, 0.f); acc.w = fmaxf(acc.w, 0.f);

    int tile = v >> 7, r = v & 127;
    frag_store(&g_Aimg[(size_t)tile * 4 * 4096], 4, r, lane * 4,
               acc.x, acc.y, acc.z, acc.w);
}

// =========================================================================
// Final projection with FUSED last gather.
// =========================================================================
__global__ void final_kernel(const float* __restrict__ ow,
                             const float* __restrict__ ob,
                             float* __restrict__ out)
{
    int gwarp = (blockIdx.x * blockDim.x + threadIdx.x) >> 5;
    int lane = threadIdx.x & 31;
    if (gwarp >= NV) return;
    int v = gwarp;
    float4 x = ((const float4*)&g_bufA[(size_t)v * 128])[lane];
    int s = g_offs[v], e = g_offs[v + 1];
    int i = s;
    for (; i + 4 <= e; i += 4) {
        int n0 = g_entries[i + 0];
        int n1 = g_entries[i + 1];
        int n2 = g_entries[i + 2];
        int n3 = g_entries[i + 3];
        float4 h0 = ((const float4*)&g_H1[(size_t)n0 * 128])[lane];
        float4 h1 = ((const float4*)&g_H1[(size_t)n1 * 128])[lane];
        float4 h2 = ((const float4*)&g_H1[(size_t)n2 * 128])[lane];
        float4 h3 = ((const float4*)&g_H1[(size_t)n3 * 128])[lane];
        x.x += (h0.x + h1.x) + (h2.x + h3.x);
        x.y += (h0.y + h1.y) + (h2.y + h3.y);
        x.z += (h0.z + h1.z) + (h2.z + h3.z);
        x.w += (h0.w + h1.w) + (h2.w + h3.w);
    }
    for (; i < e; i++) {
        int nb = g_entries[i];
        float4 h = ((const float4*)&g_H1[(size_t)nb * 128])[lane];
        x.x += h.x; x.y += h.y; x.z += h.z; x.w += h.w;
    }
    x.x = fmaxf(x.x, 0.f); x.y = fmaxf(x.y, 0.f);
    x.z = fmaxf(x.z, 0.f); x.w = fmaxf(x.w, 0.f);
    const float* wr = &ow[(size_t)(lane * 4) * 3];
    float s0 = x.x * wr[0] + x.y * wr[3] + x.z * wr[6] + x.w * wr[9];
    float s1 = x.x * wr[1] + x.y * wr[4] + x.z * wr[7] + x.w * wr[10];
    float s2 = x.x * wr[2] + x.y * wr[5] + x.z * wr[8] + x.w * wr[11];
#pragma unroll
    for (int o = 16; o > 0; o >>= 1) {
        s0 += __shfl_down_sync(0xffffffffu, s0, o);
        s1 += __shfl_down_sync(0xffffffffu, s1, o);
        s2 += __shfl_down_sync(0xffffffffu, s2, o);
    }
    if (lane == 0) {
        out[(size_t)v * 3 + 0] = s0 + ob[0];
        out[(size_t)v * 3 + 1] = s1 + ob[1];
        out[(size_t)v * 3 + 2] = s2 + ob[2];
    }
}

// =========================================================================
extern "C" void kernel_launch(void* const* d_in, const int* in_sizes, int n_in,
                              void* d_out, int out_size)
{
    const float* f1   = (const float*)d_in[0];
    const float* f2   = (const float*)d_in[1];
    const float* f3   = (const float*)d_in[2];
    const float* f4   = (const float*)d_in[3];
    const float* av   = (const float*)d_in[4];
    const float* vp   = (const float*)d_in[5];
    const float* enc  = (const float*)d_in[6];
    const int*   edges = (const int*)d_in[7];
    const float* bw   = (const float*)d_in[8];
    const float* bb   = (const float*)d_in[9];
    const float* g0w0 = (const float*)d_in[10];
    const float* g0b0 = (const float*)d_in[11];
    const float* g0w1 = (const float*)d_in[12];
    const float* g0b1 = (const float*)d_in[13];
    const float* gw0  = (const float*)d_in[14];
    const float* gb0  = (const float*)d_in[15];
    const float* gw1  = (const float*)d_in[16];
    const float* gb1  = (const float*)d_in[17];
    const float* ow   = (const float*)d_in[18];
    const float* ob   = (const float*)d_in[19];
    float* out = (float*)d_out;

    int E = in_sizes[7] / 2;

    cudaFuncSetAttribute(gemm_frag,
                         cudaFuncAttributeMaxDynamicSharedMemorySize,
                         SMEM_GEMM_BYTES);

    const int WARP_GRID = (NV + 7) / 8;
    const int G64 = (NV + 63) / 64;    // 641

    uint32_t* X0img;
    uint32_t* Aimg;
    cudaGetSymbolAddress((void**)&X0img, g_X0img);
    cudaGetSymbolAddress((void**)&Aimg,  g_Aimg);

    // (1) zero P + weight prepack fused
    init_kernel<<<ZP_BLOCKS + PP_BLOCKS, 256>>>(g0w0, g0w1, gw0, gw1);
    // (2) P tables, (3) sampler -> layer-0 fragment images
    precompute_kernel<<<396, 128>>>(f1, f2, f3, f4, bw);
    sampler_kernel<<<WARP_GRID, 256>>>(av, vp, enc, bb);
    // (4) layer-0 GEMM (cp.async pipelined, 13 chunks)
    gemm_frag<<<G64, 256, SMEM_GEMM_BYTES>>>(X0img, 13, 0, g0b0, g0b1);

    // CSR build
    zero_cnt_kernel<<<(NV + 255) / 256, 256>>>();
    hist_kernel<<<(E + 255) / 256, 256>>>(edges, E);
    scan_kernel<<<1, 1024>>>();
    fill_kernel<<<(E + 255) / 256, 256>>>(edges, E);

    // layers 1..7: gather_pack -> pipelined GEMM (4 chunks)
    for (int i = 0; i < 7; i++) {
        gather_pack<<<WARP_GRID, 256>>>();
        gemm_frag<<<G64, 256, SMEM_GEMM_BYTES>>>(Aimg, 4, 13 + i * 4,
                                gb0 + (size_t)i * 128,
                                gb1 + (size_t)i * 128);
    }

    // final: fused last gather + relu + projection
    final_kernel<<<WARP_GRID, 256>>>(ow, ob, out);
}